// round 1
// baseline (speedup 1.0000x reference)
#include <cuda_runtime.h>
#include <math.h>

#define NB 4
#define NH 16
#define DH 64
#define SQ 1024
#define LI 128
#define HIDDEN 1024
#define BHN (NB * NH)

#define BL 32
#define BR 32
#define SD 68   // padded row stride (floats) for [rows][64] tiles

// Scratch (allocation-free rule: __device__ globals)
__device__ float g_Q[BHN * SQ * DH];
__device__ float g_K[BHN * SQ * DH];
__device__ float g_V[BHN * SQ * DH];
__device__ float g_IK[BHN * LI * DH];
__device__ float g_IV[BHN * LI * DH];

// ---------------------------------------------------------------------------
// Projection GEMM: out_heads[(b*NH+h)*Slen + t][d] = X[m,:] @ W[:,n] + bias[n]
// with m = b*Slen + t, n = h*64 + d.  BM=BN=128, BK=8, TM=TN=8, 256 threads.
// ---------------------------------------------------------------------------
__global__ __launch_bounds__(256, 2)
void proj_kernel(const float* __restrict__ X, const float* __restrict__ W,
                 const float* __restrict__ bias, float* __restrict__ outp,
                 int Slen)
{
    __shared__ float As[8][132];
    __shared__ float Bs[8][132];
    const int tid = threadIdx.x;
    const int m0 = blockIdx.y * 128;
    const int n0 = blockIdx.x * 128;
    const int tx = tid & 15, ty = tid >> 4;
    const int arow = tid >> 1, acol = (tid & 1) * 4;
    const int brow = tid >> 5, bcol = (tid & 31) * 4;

    float acc[8][8];
#pragma unroll
    for (int i = 0; i < 8; i++)
#pragma unroll
        for (int j = 0; j < 8; j++) acc[i][j] = 0.f;

    const float* Aptr = X + (size_t)(m0 + arow) * HIDDEN + acol;
    const float* Bptr = W + (size_t)brow * HIDDEN + n0 + bcol;

    for (int k0 = 0; k0 < HIDDEN; k0 += 8) {
        float4 a = *(const float4*)(Aptr + k0);
        float4 bv4 = *(const float4*)(Bptr + (size_t)k0 * HIDDEN);
        __syncthreads();
        As[acol + 0][arow] = a.x;
        As[acol + 1][arow] = a.y;
        As[acol + 2][arow] = a.z;
        As[acol + 3][arow] = a.w;
        *(float4*)&Bs[brow][bcol] = bv4;
        __syncthreads();
#pragma unroll
        for (int k = 0; k < 8; k++) {
            float av[8], bv[8];
            *(float4*)&av[0] = *(const float4*)&As[k][ty * 8];
            *(float4*)&av[4] = *(const float4*)&As[k][ty * 8 + 4];
            *(float4*)&bv[0] = *(const float4*)&Bs[k][tx * 8];
            *(float4*)&bv[4] = *(const float4*)&Bs[k][tx * 8 + 4];
#pragma unroll
            for (int i = 0; i < 8; i++)
#pragma unroll
                for (int j = 0; j < 8; j++)
                    acc[i][j] = fmaf(av[i], bv[j], acc[i][j]);
        }
    }

#pragma unroll
    for (int i = 0; i < 8; i++) {
        int m = m0 + ty * 8 + i;
        int bidx = m / Slen;
        int t = m - bidx * Slen;
#pragma unroll
        for (int j = 0; j < 8; j++) {
            int n = n0 + tx * 8 + j;
            float c = acc[i][j] + bias[n];
            outp[(((size_t)bidx * NH + (n >> 6)) * Slen + t) * DH + (n & 63)] = c;
        }
    }
}

// ---------------------------------------------------------------------------
// Fused attention (flash-style, fp32).
// Block: 256 threads = 32 rows x 8 lanes. Each thread: row li = tid>>3,
// score cols ri = (tid&7)+8j (j<4), PV accumulator d-slice d0=(tid&7)*8.
// s[l,r] = q_l.k_r + (q_l+k_r).e_{l-r} ; e window (63 rows) in smem per tile.
// ---------------------------------------------------------------------------
__global__ __launch_bounds__(256, 2)
void attn_kernel(const float* __restrict__ amask, const float* __restrict__ imask,
                 const float* __restrict__ gate, const float* __restrict__ dist,
                 float* __restrict__ outp)
{
    __shared__ float Qs[BL][SD];
    __shared__ float Ks[BR][SD];
    __shared__ float Vs[BR][SD];
    __shared__ float Es[64][SD];
    __shared__ float Ss[BL][BR + 4];

    const int tid = threadIdx.x;
    const int bh = blockIdx.y;
    const int b = bh >> 4, h = bh & 15;
    const int l0 = blockIdx.x * BL;
    const int li = tid >> 3, tx = tid & 7;
    const int d0 = tx * 8;

    const float* Qg = g_Q + ((size_t)bh * SQ + l0) * DH;
    for (int i = tid; i < BL * 16; i += 256) {
        int r = i >> 4, c = (i & 15) << 2;
        *(float4*)&Qs[r][c] = *(const float4*)&Qg[r * DH + c];
    }

    float acc[8];
#pragma unroll
    for (int j = 0; j < 8; j++) acc[j] = 0.f;
    float mrow = -1e30f, ssum = 0.f;

    const float* qrow = &Qs[li][0];
    const float* krow0 = &Ks[tx][0];                 // + 8j*SD -> Ks[tx+8j]
    const float* erow0 = &Es[li - tx + 31][0];       // - 8j*SD -> Es[li-ri+31]
    const float* prow = &Ss[li][0];

    // ------------------- main attention over S keys -------------------
    for (int r0 = 0; r0 < SQ; r0 += BR) {
        __syncthreads();
        const float* Kg = g_K + ((size_t)bh * SQ + r0) * DH;
        const float* Vg = g_V + ((size_t)bh * SQ + r0) * DH;
        for (int i = tid; i < BR * 16; i += 256) {
            int r = i >> 4, c = (i & 15) << 2;
            *(float4*)&Ks[r][c] = *(const float4*)&Kg[r * DH + c];
            *(float4*)&Vs[r][c] = *(const float4*)&Vg[r * DH + c];
        }
        // E window: rows w in [0,63), global row = l0 - r0 + 992 + w  (in [0,2046])
        const float* Eg = dist + (size_t)(l0 - r0 + 992) * DH;
        for (int i = tid; i < 63 * 16; i += 256) {
            int r = i >> 4, c = (i & 15) << 2;
            *(float4*)&Es[r][c] = *(const float4*)&Eg[r * DH + c];
        }
        __syncthreads();

        float s[4] = {0.f, 0.f, 0.f, 0.f};
#pragma unroll 4
        for (int d4 = 0; d4 < 16; d4++) {
            float4 q4 = *(const float4*)(qrow + d4 * 4);
#pragma unroll
            for (int j = 0; j < 4; j++) {
                float4 k4 = *(const float4*)(krow0 + j * 8 * SD + d4 * 4);
                float4 e4 = *(const float4*)(erow0 - j * 8 * SD + d4 * 4);
                s[j] = fmaf(q4.x, k4.x + e4.x, fmaf(k4.x, e4.x, s[j]));
                s[j] = fmaf(q4.y, k4.y + e4.y, fmaf(k4.y, e4.y, s[j]));
                s[j] = fmaf(q4.z, k4.z + e4.z, fmaf(k4.z, e4.z, s[j]));
                s[j] = fmaf(q4.w, k4.w + e4.w, fmaf(k4.w, e4.w, s[j]));
            }
        }
        float mt = -1e30f;
#pragma unroll
        for (int j = 0; j < 4; j++) {
            s[j] = fmaf(s[j], 0.125f, amask[b * SQ + r0 + tx + 8 * j]);
            mt = fmaxf(mt, s[j]);
        }
        mt = fmaxf(mt, __shfl_xor_sync(0xffffffffu, mt, 1));
        mt = fmaxf(mt, __shfl_xor_sync(0xffffffffu, mt, 2));
        mt = fmaxf(mt, __shfl_xor_sync(0xffffffffu, mt, 4));
        float mnew = fmaxf(mrow, mt);
        float corr = __expf(mrow - mnew);
        float ps = 0.f;
#pragma unroll
        for (int j = 0; j < 4; j++) {
            float p = __expf(s[j] - mnew);
            Ss[li][tx + 8 * j] = p;
            ps += p;
        }
        ps += __shfl_xor_sync(0xffffffffu, ps, 1);
        ps += __shfl_xor_sync(0xffffffffu, ps, 2);
        ps += __shfl_xor_sync(0xffffffffu, ps, 4);
        ssum = ssum * corr + ps;
        mrow = mnew;
#pragma unroll
        for (int j = 0; j < 8; j++) acc[j] *= corr;
        __syncthreads();
#pragma unroll 4
        for (int r = 0; r < BR; r++) {
            float p = prow[r];
            float4 v0 = *(const float4*)&Vs[r][d0];
            float4 v1 = *(const float4*)&Vs[r][d0 + 4];
            acc[0] = fmaf(p, v0.x, acc[0]);
            acc[1] = fmaf(p, v0.y, acc[1]);
            acc[2] = fmaf(p, v0.z, acc[2]);
            acc[3] = fmaf(p, v0.w, acc[3]);
            acc[4] = fmaf(p, v1.x, acc[4]);
            acc[5] = fmaf(p, v1.y, acc[5]);
            acc[6] = fmaf(p, v1.z, acc[6]);
            acc[7] = fmaf(p, v1.w, acc[7]);
        }
    }

    float ctx[8];
    float rn = 1.f / ssum;
#pragma unroll
    for (int j = 0; j < 8; j++) { ctx[j] = acc[j] * rn; acc[j] = 0.f; }
    mrow = -1e30f; ssum = 0.f;

    // ------------------- instruct attention over L keys -------------------
    for (int r0 = 0; r0 < LI; r0 += BR) {
        __syncthreads();
        const float* Kg = g_IK + ((size_t)bh * LI + r0) * DH;
        const float* Vg = g_IV + ((size_t)bh * LI + r0) * DH;
        for (int i = tid; i < BR * 16; i += 256) {
            int r = i >> 4, c = (i & 15) << 2;
            *(float4*)&Ks[r][c] = *(const float4*)&Kg[r * DH + c];
            *(float4*)&Vs[r][c] = *(const float4*)&Vg[r * DH + c];
        }
        __syncthreads();

        float s[4] = {0.f, 0.f, 0.f, 0.f};
#pragma unroll 4
        for (int d4 = 0; d4 < 16; d4++) {
            float4 q4 = *(const float4*)(qrow + d4 * 4);
#pragma unroll
            for (int j = 0; j < 4; j++) {
                float4 k4 = *(const float4*)(krow0 + j * 8 * SD + d4 * 4);
                s[j] = fmaf(q4.x, k4.x, s[j]);
                s[j] = fmaf(q4.y, k4.y, s[j]);
                s[j] = fmaf(q4.z, k4.z, s[j]);
                s[j] = fmaf(q4.w, k4.w, s[j]);
            }
        }
        float mt = -1e30f;
#pragma unroll
        for (int j = 0; j < 4; j++) {
            s[j] = fmaf(s[j], 0.125f, imask[b * LI + r0 + tx + 8 * j]);
            mt = fmaxf(mt, s[j]);
        }
        mt = fmaxf(mt, __shfl_xor_sync(0xffffffffu, mt, 1));
        mt = fmaxf(mt, __shfl_xor_sync(0xffffffffu, mt, 2));
        mt = fmaxf(mt, __shfl_xor_sync(0xffffffffu, mt, 4));
        float mnew = fmaxf(mrow, mt);
        float corr = __expf(mrow - mnew);
        float ps = 0.f;
#pragma unroll
        for (int j = 0; j < 4; j++) {
            float p = __expf(s[j] - mnew);
            Ss[li][tx + 8 * j] = p;
            ps += p;
        }
        ps += __shfl_xor_sync(0xffffffffu, ps, 1);
        ps += __shfl_xor_sync(0xffffffffu, ps, 2);
        ps += __shfl_xor_sync(0xffffffffu, ps, 4);
        ssum = ssum * corr + ps;
        mrow = mnew;
#pragma unroll
        for (int j = 0; j < 8; j++) acc[j] *= corr;
        __syncthreads();
#pragma unroll 4
        for (int r = 0; r < BR; r++) {
            float p = prow[r];
            float4 v0 = *(const float4*)&Vs[r][d0];
            float4 v1 = *(const float4*)&Vs[r][d0 + 4];
            acc[0] = fmaf(p, v0.x, acc[0]);
            acc[1] = fmaf(p, v0.y, acc[1]);
            acc[2] = fmaf(p, v0.z, acc[2]);
            acc[3] = fmaf(p, v0.w, acc[3]);
            acc[4] = fmaf(p, v1.x, acc[4]);
            acc[5] = fmaf(p, v1.y, acc[5]);
            acc[6] = fmaf(p, v1.z, acc[6]);
            acc[7] = fmaf(p, v1.w, acc[7]);
        }
    }

    float tg = tanhf(gate[h]);
    float rn2 = 1.f / ssum;
    float* og = outp + ((size_t)(b * SQ + l0 + li)) * HIDDEN + h * DH + d0;
    float4 o0, o1;
    o0.x = ctx[0] + tg * acc[0] * rn2;
    o0.y = ctx[1] + tg * acc[1] * rn2;
    o0.z = ctx[2] + tg * acc[2] * rn2;
    o0.w = ctx[3] + tg * acc[3] * rn2;
    o1.x = ctx[4] + tg * acc[4] * rn2;
    o1.y = ctx[5] + tg * acc[5] * rn2;
    o1.z = ctx[6] + tg * acc[6] * rn2;
    o1.w = ctx[7] + tg * acc[7] * rn2;
    *(float4*)&og[0] = o0;
    *(float4*)&og[4] = o1;
}

// ---------------------------------------------------------------------------
extern "C" void kernel_launch(void* const* d_in, const int* in_sizes, int n_in,
                              void* d_out, int out_size)
{
    (void)in_sizes; (void)n_in; (void)out_size;
    const float* hs    = (const float*)d_in[0];
    const float* amask = (const float*)d_in[1];
    const float* ihs   = (const float*)d_in[2];
    const float* imask = (const float*)d_in[3];
    const float* Wq    = (const float*)d_in[4];
    const float* bq    = (const float*)d_in[5];
    const float* Wk    = (const float*)d_in[6];
    const float* bk    = (const float*)d_in[7];
    const float* Wv    = (const float*)d_in[8];
    const float* bv    = (const float*)d_in[9];
    const float* gate  = (const float*)d_in[10];
    const float* dist  = (const float*)d_in[11];
    float* out = (float*)d_out;

    float *qp, *kp, *vp, *ikp, *ivp;
    cudaGetSymbolAddress((void**)&qp, g_Q);
    cudaGetSymbolAddress((void**)&kp, g_K);
    cudaGetSymbolAddress((void**)&vp, g_V);
    cudaGetSymbolAddress((void**)&ikp, g_IK);
    cudaGetSymbolAddress((void**)&ivp, g_IV);

    dim3 g1(HIDDEN / 128, (NB * SQ) / 128);   // (8, 32)
    dim3 g2(HIDDEN / 128, (NB * LI) / 128);   // (8, 4)
    proj_kernel<<<g1, 256>>>(hs, Wq, bq, qp, SQ);
    proj_kernel<<<g1, 256>>>(hs, Wk, bk, kp, SQ);
    proj_kernel<<<g1, 256>>>(hs, Wv, bv, vp, SQ);
    proj_kernel<<<g2, 256>>>(ihs, Wk, bk, ikp, LI);
    proj_kernel<<<g2, 256>>>(ihs, Wv, bv, ivp, LI);

    attn_kernel<<<dim3(SQ / BL, BHN), 256>>>(amask, imask, gate, dist, out);
}

// round 2
// speedup vs baseline: 1.8886x; 1.8886x over previous
#include <cuda_runtime.h>
#include <math.h>

typedef unsigned long long u64;

#define NB 4
#define NH 16
#define DH 64
#define SQ 1024
#define LI 128
#define HIDDEN 1024
#define BHN (NB * NH)

// Scratch (allocation-free rule: __device__ globals)
__device__ float g_Q[BHN * SQ * DH];
__device__ float g_K[BHN * SQ * DH];
__device__ float g_V[BHN * SQ * DH];
__device__ float g_IK[BHN * LI * DH];
__device__ float g_IV[BHN * LI * DH];

// ---- packed fp32x2 helpers (sm_103a; ptxas never emits these from C++) ----
__device__ __forceinline__ u64 fma2(u64 a, u64 b, u64 c) {
    u64 r; asm("fma.rn.f32x2 %0,%1,%2,%3;" : "=l"(r) : "l"(a), "l"(b), "l"(c)); return r;
}
__device__ __forceinline__ u64 add2(u64 a, u64 b) {
    u64 r; asm("add.rn.f32x2 %0,%1,%2;" : "=l"(r) : "l"(a), "l"(b)); return r;
}
__device__ __forceinline__ u64 mul2(u64 a, u64 b) {
    u64 r; asm("mul.rn.f32x2 %0,%1,%2;" : "=l"(r) : "l"(a), "l"(b)); return r;
}
__device__ __forceinline__ u64 bc2(float a) {
    u64 r; asm("mov.b64 %0,{%1,%1};" : "=l"(r) : "f"(a)); return r;
}
__device__ __forceinline__ float2 u2f(u64 v) {
    float2 r; asm("mov.b64 {%0,%1},%2;" : "=f"(r.x), "=f"(r.y) : "l"(v)); return r;
}

// ---------------------------------------------------------------------------
// Fused QKV projection: X[4096,1024] @ (Wq|Wk|Wv). BM=BN=128, BK=8, 8x8 micro
// with f32x2 accumulation. grid (24, 32).
// ---------------------------------------------------------------------------
__global__ __launch_bounds__(256, 2)
void proj_qkv(const float* __restrict__ X,
              const float* __restrict__ Wq, const float* __restrict__ Wk,
              const float* __restrict__ Wv,
              const float* __restrict__ bq, const float* __restrict__ bk,
              const float* __restrict__ bv,
              float* __restrict__ oQ, float* __restrict__ oK, float* __restrict__ oV)
{
    __shared__ float As[8][132];
    __shared__ float Bs[8][132];
    const int tid = threadIdx.x;
    const int m0 = blockIdx.y * 128;
    const int n0g = blockIdx.x * 128;
    const int wsel = n0g >> 10;
    const int n0 = n0g & 1023;
    const float* W    = (wsel == 0) ? Wq : ((wsel == 1) ? Wk : Wv);
    const float* bias = (wsel == 0) ? bq : ((wsel == 1) ? bk : bv);
    float* outp       = (wsel == 0) ? oQ : ((wsel == 1) ? oK : oV);

    const int tx = tid & 15, ty = tid >> 4;
    const int arow = tid >> 1, acol = (tid & 1) * 4;
    const int brow = tid >> 5, bcol = (tid & 31) * 4;

    u64 acc[8][4];
#pragma unroll
    for (int i = 0; i < 8; i++)
#pragma unroll
        for (int p = 0; p < 4; p++) acc[i][p] = 0ull;

    const float* Aptr = X + (size_t)(m0 + arow) * HIDDEN + acol;
    const float* Bptr = W + (size_t)brow * HIDDEN + n0 + bcol;

    for (int k0 = 0; k0 < HIDDEN; k0 += 8) {
        float4 a  = *(const float4*)(Aptr + k0);
        float4 bb = *(const float4*)(Bptr + (size_t)k0 * HIDDEN);
        __syncthreads();
        As[acol + 0][arow] = a.x;
        As[acol + 1][arow] = a.y;
        As[acol + 2][arow] = a.z;
        As[acol + 3][arow] = a.w;
        *(float4*)&Bs[brow][bcol] = bb;
        __syncthreads();
#pragma unroll
        for (int k = 0; k < 8; k++) {
            float av[8];
            *(float4*)&av[0] = *(const float4*)&As[k][ty * 8];
            *(float4*)&av[4] = *(const float4*)&As[k][ty * 8 + 4];
            ulonglong2 b0 = *(const ulonglong2*)&Bs[k][tx * 8];
            ulonglong2 b1 = *(const ulonglong2*)&Bs[k][tx * 8 + 4];
#pragma unroll
            for (int i = 0; i < 8; i++) {
                u64 ab = bc2(av[i]);
                acc[i][0] = fma2(ab, b0.x, acc[i][0]);
                acc[i][1] = fma2(ab, b0.y, acc[i][1]);
                acc[i][2] = fma2(ab, b1.x, acc[i][2]);
                acc[i][3] = fma2(ab, b1.y, acc[i][3]);
            }
        }
    }

#pragma unroll
    for (int i = 0; i < 8; i++) {
        int m = m0 + ty * 8 + i;
        int bidx = m >> 10, t = m & 1023;
#pragma unroll
        for (int p = 0; p < 4; p++) {
            float2 c = u2f(acc[i][p]);
            int n = n0 + tx * 8 + 2 * p;
            float2 st;
            st.x = c.x + bias[n];
            st.y = c.y + bias[n + 1];
            *(float2*)(outp + (((size_t)bidx * NH + (n >> 6)) * SQ + t) * DH + (n & 63)) = st;
        }
    }
}

// ---------------------------------------------------------------------------
// Fused instruct K|V projection: X[512,1024] @ (Wk|Wv). BM=64, BN=128, BK=8,
// 4x8 micro with f32x2. grid (16, 8) = 128 blocks (was 32 -> latency-bound).
// ---------------------------------------------------------------------------
__global__ __launch_bounds__(256, 2)
void proj_ikv(const float* __restrict__ X,
              const float* __restrict__ Wk, const float* __restrict__ Wv,
              const float* __restrict__ bk, const float* __restrict__ bv,
              float* __restrict__ oK, float* __restrict__ oV)
{
    __shared__ float As[8][68];
    __shared__ float Bs[8][132];
    const int tid = threadIdx.x;
    const int m0 = blockIdx.y * 64;
    const int n0g = blockIdx.x * 128;
    const int wsel = n0g >> 10;
    const int n0 = n0g & 1023;
    const float* W    = wsel ? Wv : Wk;
    const float* bias = wsel ? bv : bk;
    float* outp       = wsel ? oV : oK;

    const int tx = tid & 15, ty = tid >> 4;
    const int arow = tid >> 2, acol = (tid & 3) * 2;
    const int brow = tid >> 5, bcol = (tid & 31) * 4;

    u64 acc[4][4];
#pragma unroll
    for (int i = 0; i < 4; i++)
#pragma unroll
        for (int p = 0; p < 4; p++) acc[i][p] = 0ull;

    const float* Aptr = X + (size_t)(m0 + arow) * HIDDEN + acol;
    const float* Bptr = W + (size_t)brow * HIDDEN + n0 + bcol;

    for (int k0 = 0; k0 < HIDDEN; k0 += 8) {
        float2 a  = *(const float2*)(Aptr + k0);
        float4 bb = *(const float4*)(Bptr + (size_t)k0 * HIDDEN);
        __syncthreads();
        As[acol + 0][arow] = a.x;
        As[acol + 1][arow] = a.y;
        *(float4*)&Bs[brow][bcol] = bb;
        __syncthreads();
#pragma unroll
        for (int k = 0; k < 8; k++) {
            float av[4];
            *(float4*)&av[0] = *(const float4*)&As[k][ty * 4];
            ulonglong2 b0 = *(const ulonglong2*)&Bs[k][tx * 8];
            ulonglong2 b1 = *(const ulonglong2*)&Bs[k][tx * 8 + 4];
#pragma unroll
            for (int i = 0; i < 4; i++) {
                u64 ab = bc2(av[i]);
                acc[i][0] = fma2(ab, b0.x, acc[i][0]);
                acc[i][1] = fma2(ab, b0.y, acc[i][1]);
                acc[i][2] = fma2(ab, b1.x, acc[i][2]);
                acc[i][3] = fma2(ab, b1.y, acc[i][3]);
            }
        }
    }

#pragma unroll
    for (int i = 0; i < 4; i++) {
        int m = m0 + ty * 4 + i;
        int bidx = m >> 7, t = m & 127;
#pragma unroll
        for (int p = 0; p < 4; p++) {
            float2 c = u2f(acc[i][p]);
            int n = n0 + tx * 8 + 2 * p;
            float2 st;
            st.x = c.x + bias[n];
            st.y = c.y + bias[n + 1];
            *(float2*)(outp + (((size_t)bidx * NH + (n >> 6)) * LI + t) * DH + (n & 63)) = st;
        }
    }
}

// ---------------------------------------------------------------------------
// Fused attention. BL=BR=64, 256 threads = 16x16 grid, each thread a 4x4
// score micro-tile (rows ty*4.., cols tx*4..) and a 4x4 PV micro-tile
// (rows ty*4.., d-slice tx*4..). Swizzled smem (slot ^= (row>>2)&7) kills
// the strided-row bank conflicts; q/p loads are warp-broadcast.
// s[l,r] = q.k + (q+k).e_{l-r}. Dynamic smem 99 KB, 2 CTAs/SM.
// ---------------------------------------------------------------------------
__device__ __forceinline__ void load_sw(float* dst, const float* src, int rows, int tid)
{
    for (int idx = tid; idx < rows * 16; idx += 256) {
        int r = idx >> 4, sl = idx & 15;
        *(float4*)(dst + r * 64 + ((sl ^ ((r >> 2) & 7)) << 2)) =
            *(const float4*)(src + (size_t)r * 64 + sl * 4);
    }
}

__global__ __launch_bounds__(256, 2)
void attn_kernel(const float* __restrict__ amask, const float* __restrict__ imask,
                 const float* __restrict__ gate, const float* __restrict__ dist,
                 float* __restrict__ outp)
{
    extern __shared__ float sm[];
    float* Qs = sm;             // 64*64
    float* Ks = sm + 4096;      // 64*64
    float* Vs = sm + 8192;      // 64*64
    float* Es = sm + 12288;     // 127*64
    float* Ss = sm + 20416;     // 64*68

    const int tid = threadIdx.x;
    const int ty = tid >> 4, tx = tid & 15;
    const int bh = blockIdx.y, b = bh >> 4, h = bh & 15;
    const int l0 = blockIdx.x * 64;
    const int w0 = 4 * ty - 4 * tx + 60;

    load_sw(Qs, g_Q + ((size_t)bh * SQ + l0) * DH, 64, tid);

    u64 acc[4][2];
    float mrow[4], ssum[4];
#pragma unroll
    for (int i = 0; i < 4; i++) {
        acc[i][0] = 0ull; acc[i][1] = 0ull;
        mrow[i] = -1e30f; ssum[i] = 0.f;
    }

    // ======================= main attention over S keys =======================
    for (int r0 = 0; r0 < SQ; r0 += 64) {
        __syncthreads();
        load_sw(Ks, g_K + ((size_t)bh * SQ + r0) * DH, 64, tid);
        load_sw(Vs, g_V + ((size_t)bh * SQ + r0) * DH, 64, tid);
        load_sw(Es, dist + (size_t)(l0 - r0 + 960) * DH, 127, tid);
        __syncthreads();

        u64 s2[4][4];
#pragma unroll
        for (int i = 0; i < 4; i++)
#pragma unroll
            for (int j = 0; j < 4; j++) s2[i][j] = 0ull;

#pragma unroll 4
        for (int d4 = 0; d4 < 16; d4++) {
            ulonglong2 kv[4], ev[7];
#pragma unroll
            for (int j = 0; j < 4; j++) {
                int r = tx * 4 + j;
                kv[j] = *(const ulonglong2*)(Ks + r * 64 + ((d4 ^ ((r >> 2) & 7)) << 2));
            }
#pragma unroll
            for (int m = 0; m < 7; m++) {
                int w = w0 + m;
                ev[m] = *(const ulonglong2*)(Es + w * 64 + ((d4 ^ ((w >> 2) & 7)) << 2));
            }
#pragma unroll
            for (int i = 0; i < 4; i++) {
                int l = ty * 4 + i;
                ulonglong2 qv = *(const ulonglong2*)(Qs + l * 64 + ((d4 ^ ((l >> 2) & 7)) << 2));
#pragma unroll
                for (int j = 0; j < 4; j++) {
                    const ulonglong2 e = ev[i - j + 3];
                    s2[i][j] = fma2(add2(qv.x, kv[j].x), e.x, s2[i][j]);
                    s2[i][j] = fma2(qv.x, kv[j].x, s2[i][j]);
                    s2[i][j] = fma2(add2(qv.y, kv[j].y), e.y, s2[i][j]);
                    s2[i][j] = fma2(qv.y, kv[j].y, s2[i][j]);
                }
            }
        }

        // -------- online softmax (rows owned per-warp across tx lanes) --------
        float mk[4];
#pragma unroll
        for (int j = 0; j < 4; j++) mk[j] = amask[b * SQ + r0 + tx * 4 + j];
#pragma unroll
        for (int i = 0; i < 4; i++) {
            float sv[4]; float mt = -1e30f;
#pragma unroll
            for (int j = 0; j < 4; j++) {
                float2 f = u2f(s2[i][j]);
                sv[j] = (f.x + f.y) * 0.125f + mk[j];
                mt = fmaxf(mt, sv[j]);
            }
            mt = fmaxf(mt, __shfl_xor_sync(0xffffffffu, mt, 1));
            mt = fmaxf(mt, __shfl_xor_sync(0xffffffffu, mt, 2));
            mt = fmaxf(mt, __shfl_xor_sync(0xffffffffu, mt, 4));
            mt = fmaxf(mt, __shfl_xor_sync(0xffffffffu, mt, 8));
            float mnew = fmaxf(mrow[i], mt);
            float corr = __expf(mrow[i] - mnew);
            mrow[i] = mnew;
            float ps = 0.f;
#pragma unroll
            for (int j = 0; j < 4; j++) {
                float p = __expf(sv[j] - mnew);
                Ss[(ty * 4 + i) * 68 + tx * 4 + j] = p;
                ps += p;
            }
            ps += __shfl_xor_sync(0xffffffffu, ps, 1);
            ps += __shfl_xor_sync(0xffffffffu, ps, 2);
            ps += __shfl_xor_sync(0xffffffffu, ps, 4);
            ps += __shfl_xor_sync(0xffffffffu, ps, 8);
            ssum[i] = ssum[i] * corr + ps;
            u64 c2 = bc2(corr);
            acc[i][0] = mul2(acc[i][0], c2);
            acc[i][1] = mul2(acc[i][1], c2);
        }
        __syncwarp();

        // ------------------------------- PV -------------------------------
#pragma unroll 2
        for (int r4 = 0; r4 < 64; r4 += 4) {
            float4 p4[4];
#pragma unroll
            for (int i = 0; i < 4; i++)
                p4[i] = *(const float4*)(Ss + (ty * 4 + i) * 68 + r4);
#pragma unroll
            for (int rr = 0; rr < 4; rr++) {
                int r = r4 + rr;
                ulonglong2 vv = *(const ulonglong2*)(Vs + r * 64 + ((tx ^ ((r >> 2) & 7)) << 2));
#pragma unroll
                for (int i = 0; i < 4; i++) {
                    float prr = (rr == 0) ? p4[i].x : (rr == 1) ? p4[i].y
                               : (rr == 2) ? p4[i].z : p4[i].w;
                    u64 pb = bc2(prr);
                    acc[i][0] = fma2(pb, vv.x, acc[i][0]);
                    acc[i][1] = fma2(pb, vv.y, acc[i][1]);
                }
            }
        }
    }

    // normalize main context, reset stats for instruct pass
    float ctxv[4][4];
#pragma unroll
    for (int i = 0; i < 4; i++) {
        float rn = 1.f / ssum[i];
        float2 f0 = u2f(acc[i][0]), f1 = u2f(acc[i][1]);
        ctxv[i][0] = f0.x * rn; ctxv[i][1] = f0.y * rn;
        ctxv[i][2] = f1.x * rn; ctxv[i][3] = f1.y * rn;
        acc[i][0] = 0ull; acc[i][1] = 0ull;
        mrow[i] = -1e30f; ssum[i] = 0.f;
    }

    // ===================== instruct attention over L keys =====================
    for (int r0 = 0; r0 < LI; r0 += 64) {
        __syncthreads();
        load_sw(Ks, g_IK + ((size_t)bh * LI + r0) * DH, 64, tid);
        load_sw(Vs, g_IV + ((size_t)bh * LI + r0) * DH, 64, tid);
        __syncthreads();

        u64 s2[4][4];
#pragma unroll
        for (int i = 0; i < 4; i++)
#pragma unroll
            for (int j = 0; j < 4; j++) s2[i][j] = 0ull;

#pragma unroll 4
        for (int d4 = 0; d4 < 16; d4++) {
            ulonglong2 kv[4];
#pragma unroll
            for (int j = 0; j < 4; j++) {
                int r = tx * 4 + j;
                kv[j] = *(const ulonglong2*)(Ks + r * 64 + ((d4 ^ ((r >> 2) & 7)) << 2));
            }
#pragma unroll
            for (int i = 0; i < 4; i++) {
                int l = ty * 4 + i;
                ulonglong2 qv = *(const ulonglong2*)(Qs + l * 64 + ((d4 ^ ((l >> 2) & 7)) << 2));
#pragma unroll
                for (int j = 0; j < 4; j++) {
                    s2[i][j] = fma2(qv.x, kv[j].x, s2[i][j]);
                    s2[i][j] = fma2(qv.y, kv[j].y, s2[i][j]);
                }
            }
        }

        float mk[4];
#pragma unroll
        for (int j = 0; j < 4; j++) mk[j] = imask[b * LI + r0 + tx * 4 + j];
#pragma unroll
        for (int i = 0; i < 4; i++) {
            float sv[4]; float mt = -1e30f;
#pragma unroll
            for (int j = 0; j < 4; j++) {
                float2 f = u2f(s2[i][j]);
                sv[j] = (f.x + f.y) * 0.125f + mk[j];
                mt = fmaxf(mt, sv[j]);
            }
            mt = fmaxf(mt, __shfl_xor_sync(0xffffffffu, mt, 1));
            mt = fmaxf(mt, __shfl_xor_sync(0xffffffffu, mt, 2));
            mt = fmaxf(mt, __shfl_xor_sync(0xffffffffu, mt, 4));
            mt = fmaxf(mt, __shfl_xor_sync(0xffffffffu, mt, 8));
            float mnew = fmaxf(mrow[i], mt);
            float corr = __expf(mrow[i] - mnew);
            mrow[i] = mnew;
            float ps = 0.f;
#pragma unroll
            for (int j = 0; j < 4; j++) {
                float p = __expf(sv[j] - mnew);
                Ss[(ty * 4 + i) * 68 + tx * 4 + j] = p;
                ps += p;
            }
            ps += __shfl_xor_sync(0xffffffffu, ps, 1);
            ps += __shfl_xor_sync(0xffffffffu, ps, 2);
            ps += __shfl_xor_sync(0xffffffffu, ps, 4);
            ps += __shfl_xor_sync(0xffffffffu, ps, 8);
            ssum[i] = ssum[i] * corr + ps;
            u64 c2 = bc2(corr);
            acc[i][0] = mul2(acc[i][0], c2);
            acc[i][1] = mul2(acc[i][1], c2);
        }
        __syncwarp();

#pragma unroll 2
        for (int r4 = 0; r4 < 64; r4 += 4) {
            float4 p4[4];
#pragma unroll
            for (int i = 0; i < 4; i++)
                p4[i] = *(const float4*)(Ss + (ty * 4 + i) * 68 + r4);
#pragma unroll
            for (int rr = 0; rr < 4; rr++) {
                int r = r4 + rr;
                ulonglong2 vv = *(const ulonglong2*)(Vs + r * 64 + ((tx ^ ((r >> 2) & 7)) << 2));
#pragma unroll
                for (int i = 0; i < 4; i++) {
                    float prr = (rr == 0) ? p4[i].x : (rr == 1) ? p4[i].y
                               : (rr == 2) ? p4[i].z : p4[i].w;
                    u64 pb = bc2(prr);
                    acc[i][0] = fma2(pb, vv.x, acc[i][0]);
                    acc[i][1] = fma2(pb, vv.y, acc[i][1]);
                }
            }
        }
    }

    // ------------------------------ epilogue ------------------------------
    float tg = tanhf(gate[h]);
#pragma unroll
    for (int i = 0; i < 4; i++) {
        float rn = 1.f / ssum[i];
        float2 f0 = u2f(acc[i][0]), f1 = u2f(acc[i][1]);
        float4 o;
        o.x = ctxv[i][0] + tg * f0.x * rn;
        o.y = ctxv[i][1] + tg * f0.y * rn;
        o.z = ctxv[i][2] + tg * f1.x * rn;
        o.w = ctxv[i][3] + tg * f1.y * rn;
        int l = l0 + ty * 4 + i;
        *(float4*)(outp + ((size_t)(b * SQ + l)) * HIDDEN + h * DH + tx * 4) = o;
    }
}

// ---------------------------------------------------------------------------
extern "C" void kernel_launch(void* const* d_in, const int* in_sizes, int n_in,
                              void* d_out, int out_size)
{
    (void)in_sizes; (void)n_in; (void)out_size;
    const float* hs    = (const float*)d_in[0];
    const float* amask = (const float*)d_in[1];
    const float* ihs   = (const float*)d_in[2];
    const float* imask = (const float*)d_in[3];
    const float* Wq    = (const float*)d_in[4];
    const float* bq    = (const float*)d_in[5];
    const float* Wk    = (const float*)d_in[6];
    const float* bk    = (const float*)d_in[7];
    const float* Wv    = (const float*)d_in[8];
    const float* bv    = (const float*)d_in[9];
    const float* gate  = (const float*)d_in[10];
    const float* dist  = (const float*)d_in[11];
    float* out = (float*)d_out;

    float *qp, *kp, *vp, *ikp, *ivp;
    cudaGetSymbolAddress((void**)&qp, g_Q);
    cudaGetSymbolAddress((void**)&kp, g_K);
    cudaGetSymbolAddress((void**)&vp, g_V);
    cudaGetSymbolAddress((void**)&ikp, g_IK);
    cudaGetSymbolAddress((void**)&ivp, g_IV);

    const int attn_smem = (20416 + 64 * 68) * 4;   // 99072 bytes
    cudaFuncSetAttribute(attn_kernel, cudaFuncAttributeMaxDynamicSharedMemorySize, attn_smem);

    proj_qkv<<<dim3(24, 32), 256>>>(hs, Wq, Wk, Wv, bq, bk, bv, qp, kp, vp);
    proj_ikv<<<dim3(16, 8), 256>>>(ihs, Wk, Wv, bk, bv, ikp, ivp);
    attn_kernel<<<dim3(SQ / 64, BHN), 256, attn_smem>>>(amask, imask, gate, dist, out);
}

// round 4
// speedup vs baseline: 2.4672x; 1.3063x over previous
#include <cuda_runtime.h>
#include <cuda_bf16.h>
#include <math.h>
#include <cstdint>

typedef unsigned long long u64;

#define NB 4
#define NH 16
#define DH 64
#define SQ 1024
#define LI 128
#define HIDDEN 1024
#define BHN (NB * NH)
#define KCAT 3072

// ---------------- scratch (__device__ globals; no allocs allowed) ----------
__device__ __align__(16) float g_Q[BHN * SQ * DH];
__device__ __align__(16) float g_K[BHN * SQ * DH];
__device__ __align__(16) float g_V[BHN * SQ * DH];
__device__ __align__(16) float g_IK[BHN * LI * DH];
__device__ __align__(16) float g_IV[BHN * LI * DH];

// concatenated split operands:  X: [Xh | Xh | Xl],  W(t): [Wh | Wl | Wh]
__device__ __align__(16) __nv_bfloat16 g_Xcat[NB * SQ * KCAT];
__device__ __align__(16) __nv_bfloat16 g_IXcat[NB * LI * KCAT];
__device__ __align__(16) __nv_bfloat16 g_Wcat[3 * HIDDEN * KCAT];   // [n(3072)][k'(3072)]

// ---------------- helpers ---------------------------------------------------
__device__ __forceinline__ uint32_t smem_u32(const void* p) {
    uint32_t a;
    asm("{ .reg .u64 t; cvta.to.shared.u64 t, %1; cvt.u32.u64 %0, t; }" : "=r"(a) : "l"(p));
    return a;
}
__device__ __forceinline__ void cpasync16(uint32_t dst, const void* src) {
    asm volatile("cp.async.cg.shared.global [%0], [%1], 16;" :: "r"(dst), "l"(src));
}
#define CP_COMMIT() asm volatile("cp.async.commit_group;" ::: "memory")
#define CP_WAIT(n)  asm volatile("cp.async.wait_group %0;" :: "n"(n) : "memory")

__device__ __forceinline__ void ldsm4(uint32_t& r0, uint32_t& r1, uint32_t& r2,
                                      uint32_t& r3, uint32_t addr) {
    asm volatile("ldmatrix.sync.aligned.m8n8.x4.shared.b16 {%0,%1,%2,%3}, [%4];"
                 : "=r"(r0), "=r"(r1), "=r"(r2), "=r"(r3) : "r"(addr));
}
__device__ __forceinline__ void mma16816(float* c, uint32_t a0, uint32_t a1,
                                         uint32_t a2, uint32_t a3,
                                         uint32_t b0, uint32_t b1) {
    asm volatile(
        "mma.sync.aligned.m16n8k16.row.col.f32.bf16.bf16.f32 "
        "{%0,%1,%2,%3}, {%4,%5,%6,%7}, {%8,%9}, {%0,%1,%2,%3};"
        : "+f"(c[0]), "+f"(c[1]), "+f"(c[2]), "+f"(c[3])
        : "r"(a0), "r"(a1), "r"(a2), "r"(a3), "r"(b0), "r"(b1));
}

// ---------------- f32x2 helpers (attention) --------------------------------
__device__ __forceinline__ u64 fma2(u64 a, u64 b, u64 c) {
    u64 r; asm("fma.rn.f32x2 %0,%1,%2,%3;" : "=l"(r) : "l"(a), "l"(b), "l"(c)); return r;
}
__device__ __forceinline__ u64 add2(u64 a, u64 b) {
    u64 r; asm("add.rn.f32x2 %0,%1,%2;" : "=l"(r) : "l"(a), "l"(b)); return r;
}
__device__ __forceinline__ u64 mul2(u64 a, u64 b) {
    u64 r; asm("mul.rn.f32x2 %0,%1,%2;" : "=l"(r) : "l"(a), "l"(b)); return r;
}
__device__ __forceinline__ u64 bc2(float a) {
    u64 r; asm("mov.b64 %0,{%1,%1};" : "=l"(r) : "f"(a)); return r;
}
__device__ __forceinline__ float2 u2f(u64 v) {
    float2 r; asm("mov.b64 {%0,%1},%2;" : "=f"(r.x), "=f"(r.y) : "l"(v)); return r;
}

// ---------------------------------------------------------------------------
// Conversion: X fp32 [M][1024] -> Xcat bf16 [M][3072] = [hi | hi | lo]
// ---------------------------------------------------------------------------
__global__ __launch_bounds__(256)
void conv_x(const float4* __restrict__ src, __nv_bfloat16* __restrict__ dst, int n4)
{
    int i = blockIdx.x * 256 + threadIdx.x;
    if (i >= n4) return;
    int row = i >> 8, c4 = (i & 255) * 4;
    float4 v = src[i];
    __nv_bfloat16 hx = __float2bfloat16(v.x), hy = __float2bfloat16(v.y);
    __nv_bfloat16 hz = __float2bfloat16(v.z), hw = __float2bfloat16(v.w);
    __nv_bfloat16 lx = __float2bfloat16(v.x - __bfloat162float(hx));
    __nv_bfloat16 ly = __float2bfloat16(v.y - __bfloat162float(hy));
    __nv_bfloat16 lz = __float2bfloat16(v.z - __bfloat162float(hz));
    __nv_bfloat16 lw = __float2bfloat16(v.w - __bfloat162float(hw));
    uint2 H, L;
    H.x = (uint32_t)__bfloat16_as_ushort(hx) | ((uint32_t)__bfloat16_as_ushort(hy) << 16);
    H.y = (uint32_t)__bfloat16_as_ushort(hz) | ((uint32_t)__bfloat16_as_ushort(hw) << 16);
    L.x = (uint32_t)__bfloat16_as_ushort(lx) | ((uint32_t)__bfloat16_as_ushort(ly) << 16);
    L.y = (uint32_t)__bfloat16_as_ushort(lz) | ((uint32_t)__bfloat16_as_ushort(lw) << 16);
    __nv_bfloat16* rb = dst + (size_t)row * KCAT + c4;
    *(uint2*)(rb)        = H;
    *(uint2*)(rb + 1024) = H;
    *(uint2*)(rb + 2048) = L;
}

// ---------------------------------------------------------------------------
// W transpose+split: W[k][n] f32 (3 mats) -> Wcat[n'][k'] = [hi | lo | hi]
// ---------------------------------------------------------------------------
__global__ __launch_bounds__(256)
void conv_w(const float* __restrict__ Wq, const float* __restrict__ Wk,
            const float* __restrict__ Wv, __nv_bfloat16* __restrict__ dst)
{
    const float* W = (blockIdx.z == 0) ? Wq : (blockIdx.z == 1) ? Wk : Wv;
    __shared__ float t[32][33];
    int tx = threadIdx.x & 31, ty = threadIdx.x >> 5;
    int n = blockIdx.x * 32 + tx, k0 = blockIdx.y * 32;
#pragma unroll
    for (int j = 0; j < 4; j++)
        t[ty + 8 * j][tx] = W[(size_t)(k0 + ty + 8 * j) * HIDDEN + n];
    __syncthreads();
    size_t nrow = (size_t)blockIdx.z * HIDDEN + blockIdx.x * 32;
#pragma unroll
    for (int j = 0; j < 4; j++) {
        float v = t[tx][ty + 8 * j];
        __nv_bfloat16 h = __float2bfloat16(v);
        __nv_bfloat16 l = __float2bfloat16(v - __bfloat162float(h));
        __nv_bfloat16* o = dst + (nrow + ty + 8 * j) * KCAT + k0 + tx;
        o[0]    = h;
        o[1024] = l;
        o[2048] = h;
    }
}

// ---------------------------------------------------------------------------
// bf16 mma.sync GEMM: out[m][n] = Xcat[m][:] . Wcat[n][:] + bias
// CTA 128x128, 8 warps (2x4, warp tile 64x32), KC=64 chunks, cp.async 2-buf.
// ---------------------------------------------------------------------------
#define KC 64
#define AST 72                      // padded row stride (bf16)
#define TILE_B (128 * AST * 2)      // 18432 bytes per operand tile
#define GEMM_SMEM (4 * TILE_B)      // 73728

__global__ __launch_bounds__(256, 2)
void gemm_mma(const __nv_bfloat16* __restrict__ A, int msh, int Slen,
              const __nv_bfloat16* __restrict__ Bm,
              const float* __restrict__ bq, const float* __restrict__ bk,
              const float* __restrict__ bv,
              float* oQ, float* oK, float* oV, int n_base)
{
    extern __shared__ char smem[];
    const uint32_t sb = smem_u32(smem);
    const int tid = threadIdx.x, warp = tid >> 5, lane = tid & 31;
    const int m0 = blockIdx.y * 128;
    const int n0g = n_base + blockIdx.x * 128;
    const int wm = (warp >> 2) * 64, wn = (warp & 3) * 32;

    const int cr = tid >> 3, cko = (tid & 7) * 8;       // copy coords
    const __nv_bfloat16* Ag = A + (size_t)(m0 + cr) * KCAT + cko;
    const __nv_bfloat16* Bg = Bm + (size_t)(n0g + cr) * KCAT + cko;
    const uint32_t sAo = (cr * AST + cko) * 2;

    float acc[4][4][4];
#pragma unroll
    for (int i = 0; i < 4; i++)
#pragma unroll
        for (int j = 0; j < 4; j++)
#pragma unroll
            for (int p = 0; p < 4; p++) acc[i][j][p] = 0.f;

    // prefetch chunk 0 into buffer 0 (each thread copies 1 row-slice x4 rows)
#pragma unroll
    for (int i = 0; i < 4; i++) {
        cpasync16(sb + sAo + i * 32 * AST * 2, Ag + (size_t)(i * 32) * KCAT);
        cpasync16(sb + TILE_B + sAo + i * 32 * AST * 2, Bg + (size_t)(i * 32) * KCAT);
    }
    CP_COMMIT();

    const int NCH = KCAT / KC;   // 48
    for (int c = 0; c < NCH; c++) {
        const int p = c & 1;
        if (c + 1 < NCH) {
            const int pn = (c + 1) & 1;
            const size_t koff = (size_t)(c + 1) * KC;
#pragma unroll
            for (int i = 0; i < 4; i++) {
                cpasync16(sb + pn * 2 * TILE_B + sAo + i * 32 * AST * 2,
                          Ag + (size_t)(i * 32) * KCAT + koff);
                cpasync16(sb + pn * 2 * TILE_B + TILE_B + sAo + i * 32 * AST * 2,
                          Bg + (size_t)(i * 32) * KCAT + koff);
            }
            CP_COMMIT();
            CP_WAIT(1);
        } else {
            CP_WAIT(0);
        }
        __syncthreads();

        const uint32_t aw = sb + p * 2 * TILE_B +
                            ((wm + (lane & 15)) * AST + (lane >> 4) * 8) * 2;
        const uint32_t bw = sb + p * 2 * TILE_B + TILE_B +
                            ((wn + (lane & 15)) * AST + (lane >> 4) * 8) * 2;
#pragma unroll
        for (int k16 = 0; k16 < 4; k16++) {
            const uint32_t ko = k16 * 32;   // 16 bf16 = 32 bytes
            uint32_t a[4][4], b[8];
#pragma unroll
            for (int mt = 0; mt < 4; mt++)
                ldsm4(a[mt][0], a[mt][1], a[mt][2], a[mt][3],
                      aw + mt * 16 * AST * 2 + ko);
            ldsm4(b[0], b[1], b[2], b[3], bw + ko);
            ldsm4(b[4], b[5], b[6], b[7], bw + 16 * AST * 2 + ko);
            // n-frags: {b0,b2} {b1,b3} {b4,b6} {b5,b7}
#pragma unroll
            for (int mt = 0; mt < 4; mt++) {
                mma16816(acc[mt][0], a[mt][0], a[mt][1], a[mt][2], a[mt][3], b[0], b[2]);
                mma16816(acc[mt][1], a[mt][0], a[mt][1], a[mt][2], a[mt][3], b[1], b[3]);
                mma16816(acc[mt][2], a[mt][0], a[mt][1], a[mt][2], a[mt][3], b[4], b[6]);
                mma16816(acc[mt][3], a[mt][0], a[mt][1], a[mt][2], a[mt][3], b[5], b[7]);
            }
        }
        __syncthreads();
    }

    // ---- epilogue: bias + head-major scatter (float2 per fragment half) ----
#pragma unroll
    for (int nt = 0; nt < 4; nt++) {
        const int n = n0g + wn + nt * 8 + (lane & 3) * 2;
        const int wsel = n >> 10, nn = n & 1023;
        const float* bias = (wsel == 0) ? bq : (wsel == 1) ? bk : bv;
        float* outp = (wsel == 0) ? oQ : (wsel == 1) ? oK : oV;
        const float b0 = bias[nn], b1 = bias[nn + 1];
        const size_t hoff = ((size_t)(nn >> 6)) * Slen;
        const int d = nn & 63;
#pragma unroll
        for (int mt = 0; mt < 4; mt++) {
            const int r0 = m0 + wm + mt * 16 + (lane >> 2);
            const int bb0 = r0 >> msh, t0 = r0 - (bb0 << msh);
            float2 v0 = { acc[mt][nt][0] + b0, acc[mt][nt][1] + b1 };
            *(float2*)(outp + ((size_t)bb0 * NH * Slen + hoff + t0) * DH + d) = v0;
            const int r1 = r0 + 8;
            const int bb1 = r1 >> msh, t1 = r1 - (bb1 << msh);
            float2 v1 = { acc[mt][nt][2] + b0, acc[mt][nt][3] + b1 };
            *(float2*)(outp + ((size_t)bb1 * NH * Slen + hoff + t1) * DH + d) = v1;
        }
    }
}

// ---------------------------------------------------------------------------
// Fused attention (unchanged, proven): BL=BR=64, f32x2, swizzled smem.
// ---------------------------------------------------------------------------
__device__ __forceinline__ void load_sw(float* dst, const float* src, int rows, int tid)
{
    for (int idx = tid; idx < rows * 16; idx += 256) {
        int r = idx >> 4, sl = idx & 15;
        *(float4*)(dst + r * 64 + ((sl ^ ((r >> 2) & 7)) << 2)) =
            *(const float4*)(src + (size_t)r * 64 + sl * 4);
    }
}

__global__ __launch_bounds__(256, 2)
void attn_kernel(const float* __restrict__ amask, const float* __restrict__ imask,
                 const float* __restrict__ gate, const float* __restrict__ dist,
                 float* __restrict__ outp)
{
    extern __shared__ float sm[];
    float* Qs = sm;
    float* Ks = sm + 4096;
    float* Vs = sm + 8192;
    float* Es = sm + 12288;
    float* Ss = sm + 20416;

    const int tid = threadIdx.x;
    const int ty = tid >> 4, tx = tid & 15;
    const int bh = blockIdx.y, b = bh >> 4, h = bh & 15;
    const int l0 = blockIdx.x * 64;
    const int w0 = 4 * ty - 4 * tx + 60;

    load_sw(Qs, g_Q + ((size_t)bh * SQ + l0) * DH, 64, tid);

    u64 acc[4][2];
    float mrow[4], ssum[4];
#pragma unroll
    for (int i = 0; i < 4; i++) {
        acc[i][0] = 0ull; acc[i][1] = 0ull;
        mrow[i] = -1e30f; ssum[i] = 0.f;
    }

    for (int r0 = 0; r0 < SQ; r0 += 64) {
        __syncthreads();
        load_sw(Ks, g_K + ((size_t)bh * SQ + r0) * DH, 64, tid);
        load_sw(Vs, g_V + ((size_t)bh * SQ + r0) * DH, 64, tid);
        load_sw(Es, dist + (size_t)(l0 - r0 + 960) * DH, 127, tid);
        __syncthreads();

        u64 s2[4][4];
#pragma unroll
        for (int i = 0; i < 4; i++)
#pragma unroll
            for (int j = 0; j < 4; j++) s2[i][j] = 0ull;

#pragma unroll 4
        for (int d4 = 0; d4 < 16; d4++) {
            ulonglong2 kv[4], ev[7];
#pragma unroll
            for (int j = 0; j < 4; j++) {
                int r = tx * 4 + j;
                kv[j] = *(const ulonglong2*)(Ks + r * 64 + ((d4 ^ ((r >> 2) & 7)) << 2));
            }
#pragma unroll
            for (int m = 0; m < 7; m++) {
                int w = w0 + m;
                ev[m] = *(const ulonglong2*)(Es + w * 64 + ((d4 ^ ((w >> 2) & 7)) << 2));
            }
#pragma unroll
            for (int i = 0; i < 4; i++) {
                int l = ty * 4 + i;
                ulonglong2 qv = *(const ulonglong2*)(Qs + l * 64 + ((d4 ^ ((l >> 2) & 7)) << 2));
#pragma unroll
                for (int j = 0; j < 4; j++) {
                    const ulonglong2 e = ev[i - j + 3];
                    s2[i][j] = fma2(add2(qv.x, kv[j].x), e.x, s2[i][j]);
                    s2[i][j] = fma2(qv.x, kv[j].x, s2[i][j]);
                    s2[i][j] = fma2(add2(qv.y, kv[j].y), e.y, s2[i][j]);
                    s2[i][j] = fma2(qv.y, kv[j].y, s2[i][j]);
                }
            }
        }

        float mk[4];
#pragma unroll
        for (int j = 0; j < 4; j++) mk[j] = amask[b * SQ + r0 + tx * 4 + j];
#pragma unroll
        for (int i = 0; i < 4; i++) {
            float sv[4]; float mt = -1e30f;
#pragma unroll
            for (int j = 0; j < 4; j++) {
                float2 f = u2f(s2[i][j]);
                sv[j] = (f.x + f.y) * 0.125f + mk[j];
                mt = fmaxf(mt, sv[j]);
            }
            mt = fmaxf(mt, __shfl_xor_sync(0xffffffffu, mt, 1));
            mt = fmaxf(mt, __shfl_xor_sync(0xffffffffu, mt, 2));
            mt = fmaxf(mt, __shfl_xor_sync(0xffffffffu, mt, 4));
            mt = fmaxf(mt, __shfl_xor_sync(0xffffffffu, mt, 8));
            float mnew = fmaxf(mrow[i], mt);
            float corr = __expf(mrow[i] - mnew);
            mrow[i] = mnew;
            float ps = 0.f;
#pragma unroll
            for (int j = 0; j < 4; j++) {
                float p = __expf(sv[j] - mnew);
                Ss[(ty * 4 + i) * 68 + tx * 4 + j] = p;
                ps += p;
            }
            ps += __shfl_xor_sync(0xffffffffu, ps, 1);
            ps += __shfl_xor_sync(0xffffffffu, ps, 2);
            ps += __shfl_xor_sync(0xffffffffu, ps, 4);
            ps += __shfl_xor_sync(0xffffffffu, ps, 8);
            ssum[i] = ssum[i] * corr + ps;
            u64 c2 = bc2(corr);
            acc[i][0] = mul2(acc[i][0], c2);
            acc[i][1] = mul2(acc[i][1], c2);
        }
        __syncwarp();

#pragma unroll 2
        for (int r4 = 0; r4 < 64; r4 += 4) {
            float4 p4[4];
#pragma unroll
            for (int i = 0; i < 4; i++)
                p4[i] = *(const float4*)(Ss + (ty * 4 + i) * 68 + r4);
#pragma unroll
            for (int rr = 0; rr < 4; rr++) {
                int r = r4 + rr;
                ulonglong2 vv = *(const ulonglong2*)(Vs + r * 64 + ((tx ^ ((r >> 2) & 7)) << 2));
#pragma unroll
                for (int i = 0; i < 4; i++) {
                    float prr = (rr == 0) ? p4[i].x : (rr == 1) ? p4[i].y
                               : (rr == 2) ? p4[i].z : p4[i].w;
                    u64 pb = bc2(prr);
                    acc[i][0] = fma2(pb, vv.x, acc[i][0]);
                    acc[i][1] = fma2(pb, vv.y, acc[i][1]);
                }
            }
        }
    }

    float ctxv[4][4];
#pragma unroll
    for (int i = 0; i < 4; i++) {
        float rn = 1.f / ssum[i];
        float2 f0 = u2f(acc[i][0]), f1 = u2f(acc[i][1]);
        ctxv[i][0] = f0.x * rn; ctxv[i][1] = f0.y * rn;
        ctxv[i][2] = f1.x * rn; ctxv[i][3] = f1.y * rn;
        acc[i][0] = 0ull; acc[i][1] = 0ull;
        mrow[i] = -1e30f; ssum[i] = 0.f;
    }

    for (int r0 = 0; r0 < LI; r0 += 64) {
        __syncthreads();
        load_sw(Ks, g_IK + ((size_t)bh * LI + r0) * DH, 64, tid);
        load_sw(Vs, g_IV + ((size_t)bh * LI + r0) * DH, 64, tid);
        __syncthreads();

        u64 s2[4][4];
#pragma unroll
        for (int i = 0; i < 4; i++)
#pragma unroll
            for (int j = 0; j < 4; j++) s2[i][j] = 0ull;

#pragma unroll 4
        for (int d4 = 0; d4 < 16; d4++) {
            ulonglong2 kv[4];
#pragma unroll
            for (int j = 0; j < 4; j++) {
                int r = tx * 4 + j;
                kv[j] = *(const ulonglong2*)(Ks + r * 64 + ((d4 ^ ((r >> 2) & 7)) << 2));
            }
#pragma unroll
            for (int i = 0; i < 4; i++) {
                int l = ty * 4 + i;
                ulonglong2 qv = *(const ulonglong2*)(Qs + l * 64 + ((d4 ^ ((l >> 2) & 7)) << 2));
#pragma unroll
                for (int j = 0; j < 4; j++) {
                    s2[i][j] = fma2(qv.x, kv[j].x, s2[i][j]);
                    s2[i][j] = fma2(qv.y, kv[j].y, s2[i][j]);
                }
            }
        }

        float mk[4];
#pragma unroll
        for (int j = 0; j < 4; j++) mk[j] = imask[b * LI + r0 + tx * 4 + j];
#pragma unroll
        for (int i = 0; i < 4; i++) {
            float sv[4]; float mt = -1e30f;
#pragma unroll
            for (int j = 0; j < 4; j++) {
                float2 f = u2f(s2[i][j]);
                sv[j] = (f.x + f.y) * 0.125f + mk[j];
                mt = fmaxf(mt, sv[j]);
            }
            mt = fmaxf(mt, __shfl_xor_sync(0xffffffffu, mt, 1));
            mt = fmaxf(mt, __shfl_xor_sync(0xffffffffu, mt, 2));
            mt = fmaxf(mt, __shfl_xor_sync(0xffffffffu, mt, 4));
            mt = fmaxf(mt, __shfl_xor_sync(0xffffffffu, mt, 8));
            float mnew = fmaxf(mrow[i], mt);
            float corr = __expf(mrow[i] - mnew);
            mrow[i] = mnew;
            float ps = 0.f;
#pragma unroll
            for (int j = 0; j < 4; j++) {
                float p = __expf(sv[j] - mnew);
                Ss[(ty * 4 + i) * 68 + tx * 4 + j] = p;
                ps += p;
            }
            ps += __shfl_xor_sync(0xffffffffu, ps, 1);
            ps += __shfl_xor_sync(0xffffffffu, ps, 2);
            ps += __shfl_xor_sync(0xffffffffu, ps, 4);
            ps += __shfl_xor_sync(0xffffffffu, ps, 8);
            ssum[i] = ssum[i] * corr + ps;
            u64 c2 = bc2(corr);
            acc[i][0] = mul2(acc[i][0], c2);
            acc[i][1] = mul2(acc[i][1], c2);
        }
        __syncwarp();

#pragma unroll 2
        for (int r4 = 0; r4 < 64; r4 += 4) {
            float4 p4[4];
#pragma unroll
            for (int i = 0; i < 4; i++)
                p4[i] = *(const float4*)(Ss + (ty * 4 + i) * 68 + r4);
#pragma unroll
            for (int rr = 0; rr < 4; rr++) {
                int r = r4 + rr;
                ulonglong2 vv = *(const ulonglong2*)(Vs + r * 64 + ((tx ^ ((r >> 2) & 7)) << 2));
#pragma unroll
                for (int i = 0; i < 4; i++) {
                    float prr = (rr == 0) ? p4[i].x : (rr == 1) ? p4[i].y
                               : (rr == 2) ? p4[i].z : p4[i].w;
                    u64 pb = bc2(prr);
                    acc[i][0] = fma2(pb, vv.x, acc[i][0]);
                    acc[i][1] = fma2(pb, vv.y, acc[i][1]);
                }
            }
        }
    }

    float tg = tanhf(gate[h]);
#pragma unroll
    for (int i = 0; i < 4; i++) {
        float rn = 1.f / ssum[i];
        float2 f0 = u2f(acc[i][0]), f1 = u2f(acc[i][1]);
        float4 o;
        o.x = ctxv[i][0] + tg * f0.x * rn;
        o.y = ctxv[i][1] + tg * f0.y * rn;
        o.z = ctxv[i][2] + tg * f1.x * rn;
        o.w = ctxv[i][3] + tg * f1.y * rn;
        int l = l0 + ty * 4 + i;
        *(float4*)(outp + ((size_t)(b * SQ + l)) * HIDDEN + h * DH + tx * 4) = o;
    }
}

// ---------------------------------------------------------------------------
extern "C" void kernel_launch(void* const* d_in, const int* in_sizes, int n_in,
                              void* d_out, int out_size)
{
    (void)in_sizes; (void)n_in; (void)out_size;
    const float* hs    = (const float*)d_in[0];
    const float* amask = (const float*)d_in[1];
    const float* ihs   = (const float*)d_in[2];
    const float* imask = (const float*)d_in[3];
    const float* Wq    = (const float*)d_in[4];
    const float* bq    = (const float*)d_in[5];
    const float* Wk    = (const float*)d_in[6];
    const float* bk    = (const float*)d_in[7];
    const float* Wv    = (const float*)d_in[8];
    const float* bv    = (const float*)d_in[9];
    const float* gate  = (const float*)d_in[10];
    const float* dist  = (const float*)d_in[11];
    float* out = (float*)d_out;

    float *qp, *kp, *vp, *ikp, *ivp;
    __nv_bfloat16 *xc, *ixc, *wc;
    cudaGetSymbolAddress((void**)&qp, g_Q);
    cudaGetSymbolAddress((void**)&kp, g_K);
    cudaGetSymbolAddress((void**)&vp, g_V);
    cudaGetSymbolAddress((void**)&ikp, g_IK);
    cudaGetSymbolAddress((void**)&ivp, g_IV);
    cudaGetSymbolAddress((void**)&xc, g_Xcat);
    cudaGetSymbolAddress((void**)&ixc, g_IXcat);
    cudaGetSymbolAddress((void**)&wc, g_Wcat);

    const int attn_smem = (20416 + 64 * 68) * 4;
    cudaFuncSetAttribute(attn_kernel, cudaFuncAttributeMaxDynamicSharedMemorySize, attn_smem);
    cudaFuncSetAttribute(gemm_mma, cudaFuncAttributeMaxDynamicSharedMemorySize, GEMM_SMEM);

    conv_x<<<(NB * SQ * HIDDEN / 4 + 255) / 256, 256>>>((const float4*)hs, xc,
                                                        NB * SQ * HIDDEN / 4);
    conv_x<<<(NB * LI * HIDDEN / 4 + 255) / 256, 256>>>((const float4*)ihs, ixc,
                                                        NB * LI * HIDDEN / 4);
    conv_w<<<dim3(32, 32, 3), 256>>>(Wq, Wk, Wv, wc);

    // main QKV: M=4096, N=3072 ; instruct K|V: M=512, N in [1024,3072)
    gemm_mma<<<dim3(24, 32), 256, GEMM_SMEM>>>(xc, 10, SQ, wc, bq, bk, bv,
                                               qp, kp, vp, 0);
    gemm_mma<<<dim3(16, 4), 256, GEMM_SMEM>>>(ixc, 7, LI, wc, bq, bk, bv,
                                              qp, ikp, ivp, 1024);

    attn_kernel<<<dim3(SQ / 64, BHN), 256, attn_smem>>>(amask, imask, gate, dist, out);
}

// round 5
// speedup vs baseline: 4.2543x; 1.7243x over previous
#include <cuda_runtime.h>
#include <cuda_bf16.h>
#include <math.h>
#include <cstdint>

#define NB 4
#define NH 16
#define DH 64
#define SQ 1024
#define LI 128
#define HIDDEN 1024
#define BHN (NB * NH)
#define KCAT 3072

// ---------------- scratch ---------------------------------------------------
__device__ __align__(16) __nv_bfloat16 g_Qh[BHN * SQ * DH];
__device__ __align__(16) __nv_bfloat16 g_Ql[BHN * SQ * DH];
__device__ __align__(16) __nv_bfloat16 g_Kh[BHN * SQ * DH];
__device__ __align__(16) __nv_bfloat16 g_Kl[BHN * SQ * DH];
__device__ __align__(16) __nv_bfloat16 g_Vh[BHN * SQ * DH];
__device__ __align__(16) __nv_bfloat16 g_Vl[BHN * SQ * DH];
__device__ __align__(16) __nv_bfloat16 g_IKh[BHN * LI * DH];
__device__ __align__(16) __nv_bfloat16 g_IKl[BHN * LI * DH];
__device__ __align__(16) __nv_bfloat16 g_IVh[BHN * LI * DH];
__device__ __align__(16) __nv_bfloat16 g_IVl[BHN * LI * DH];
__device__ __align__(16) __nv_bfloat16 g_Eh[2048 * DH];

__device__ __align__(16) __nv_bfloat16 g_Xcat[NB * SQ * KCAT];
__device__ __align__(16) __nv_bfloat16 g_IXcat[NB * LI * KCAT];
__device__ __align__(16) __nv_bfloat16 g_Wcat[3 * HIDDEN * KCAT];

// ---------------- helpers ---------------------------------------------------
__device__ __forceinline__ uint32_t smem_u32(const void* p) {
    uint32_t a;
    asm("{ .reg .u64 t; cvta.to.shared.u64 t, %1; cvt.u32.u64 %0, t; }" : "=r"(a) : "l"(p));
    return a;
}
__device__ __forceinline__ void ldsm4(uint32_t& r0, uint32_t& r1, uint32_t& r2,
                                      uint32_t& r3, uint32_t addr) {
    asm volatile("ldmatrix.sync.aligned.m8n8.x4.shared.b16 {%0,%1,%2,%3}, [%4];"
                 : "=r"(r0), "=r"(r1), "=r"(r2), "=r"(r3) : "r"(addr));
}
__device__ __forceinline__ void ldsm4t(uint32_t& r0, uint32_t& r1, uint32_t& r2,
                                       uint32_t& r3, uint32_t addr) {
    asm volatile("ldmatrix.sync.aligned.m8n8.x4.trans.shared.b16 {%0,%1,%2,%3}, [%4];"
                 : "=r"(r0), "=r"(r1), "=r"(r2), "=r"(r3) : "r"(addr));
}
__device__ __forceinline__ void mma16816(float* c, uint32_t a0, uint32_t a1,
                                         uint32_t a2, uint32_t a3,
                                         uint32_t b0, uint32_t b1) {
    asm volatile(
        "mma.sync.aligned.m16n8k16.row.col.f32.bf16.bf16.f32 "
        "{%0,%1,%2,%3}, {%4,%5,%6,%7}, {%8,%9}, {%0,%1,%2,%3};"
        : "+f"(c[0]), "+f"(c[1]), "+f"(c[2]), "+f"(c[3])
        : "r"(a0), "r"(a1), "r"(a2), "r"(a3), "r"(b0), "r"(b1));
}
__device__ __forceinline__ uint32_t pk2(float a, float b) {
    __nv_bfloat162 t = __floats2bfloat162_rn(a, b);
    return *(uint32_t*)&t;
}
__device__ __forceinline__ void cpasync16(uint32_t dst, const void* src) {
    asm volatile("cp.async.cg.shared.global [%0], [%1], 16;" :: "r"(dst), "l"(src));
}
#define CP_COMMIT() asm volatile("cp.async.commit_group;" ::: "memory")
#define CP_WAIT(n)  asm volatile("cp.async.wait_group %0;" :: "n"(n) : "memory")

// ---------------------------------------------------------------------------
// Conversions (unchanged structure)
// ---------------------------------------------------------------------------
__global__ __launch_bounds__(256)
void conv_x(const float4* __restrict__ src, __nv_bfloat16* __restrict__ dst, int n4)
{
    int i = blockIdx.x * 256 + threadIdx.x;
    if (i >= n4) return;
    int row = i >> 8, c4 = (i & 255) * 4;
    float4 v = src[i];
    __nv_bfloat16 hx = __float2bfloat16(v.x), hy = __float2bfloat16(v.y);
    __nv_bfloat16 hz = __float2bfloat16(v.z), hw = __float2bfloat16(v.w);
    __nv_bfloat16 lx = __float2bfloat16(v.x - __bfloat162float(hx));
    __nv_bfloat16 ly = __float2bfloat16(v.y - __bfloat162float(hy));
    __nv_bfloat16 lz = __float2bfloat16(v.z - __bfloat162float(hz));
    __nv_bfloat16 lw = __float2bfloat16(v.w - __bfloat162float(hw));
    uint2 H, L;
    H.x = (uint32_t)__bfloat16_as_ushort(hx) | ((uint32_t)__bfloat16_as_ushort(hy) << 16);
    H.y = (uint32_t)__bfloat16_as_ushort(hz) | ((uint32_t)__bfloat16_as_ushort(hw) << 16);
    L.x = (uint32_t)__bfloat16_as_ushort(lx) | ((uint32_t)__bfloat16_as_ushort(ly) << 16);
    L.y = (uint32_t)__bfloat16_as_ushort(lz) | ((uint32_t)__bfloat16_as_ushort(lw) << 16);
    __nv_bfloat16* rb = dst + (size_t)row * KCAT + c4;
    *(uint2*)(rb)        = H;
    *(uint2*)(rb + 1024) = H;
    *(uint2*)(rb + 2048) = L;
}

__global__ __launch_bounds__(256)
void conv_w(const float* __restrict__ Wq, const float* __restrict__ Wk,
            const float* __restrict__ Wv, __nv_bfloat16* __restrict__ dst)
{
    const float* W = (blockIdx.z == 0) ? Wq : (blockIdx.z == 1) ? Wk : Wv;
    __shared__ float t[32][33];
    int tx = threadIdx.x & 31, ty = threadIdx.x >> 5;
    int n = blockIdx.x * 32 + tx, k0 = blockIdx.y * 32;
#pragma unroll
    for (int j = 0; j < 4; j++)
        t[ty + 8 * j][tx] = W[(size_t)(k0 + ty + 8 * j) * HIDDEN + n];
    __syncthreads();
    size_t nrow = (size_t)blockIdx.z * HIDDEN + blockIdx.x * 32;
#pragma unroll
    for (int j = 0; j < 4; j++) {
        float v = t[tx][ty + 8 * j];
        __nv_bfloat16 h = __float2bfloat16(v);
        __nv_bfloat16 l = __float2bfloat16(v - __bfloat162float(h));
        __nv_bfloat16* o = dst + (nrow + ty + 8 * j) * KCAT + k0 + tx;
        o[0]    = h;
        o[1024] = l;
        o[2048] = h;
    }
}

__global__ __launch_bounds__(256)
void conv_e(const float* __restrict__ dist, __nv_bfloat16* __restrict__ eh)
{
    int i = blockIdx.x * 256 + threadIdx.x;
    if (i >= 2048 * 64) return;
    float v = (i < 2047 * 64) ? dist[i] : 0.f;
    eh[i] = __float2bfloat16(v);
}

// ---------------------------------------------------------------------------
// Projection GEMM (R4 core; epilogue now writes bf16 hi/lo head-major)
// ---------------------------------------------------------------------------
#define KC 64
#define AST 72
#define TILE_B (128 * AST * 2)
#define GEMM_SMEM (4 * TILE_B)

__global__ __launch_bounds__(256, 2)
void gemm_mma(const __nv_bfloat16* __restrict__ A, int msh, int Slen,
              const __nv_bfloat16* __restrict__ Bm,
              const float* __restrict__ bq, const float* __restrict__ bk,
              const float* __restrict__ bv,
              __nv_bfloat16* oQh, __nv_bfloat16* oQl,
              __nv_bfloat16* oKh, __nv_bfloat16* oKl,
              __nv_bfloat16* oVh, __nv_bfloat16* oVl, int n_base)
{
    extern __shared__ char smem[];
    const uint32_t sb = smem_u32(smem);
    const int tid = threadIdx.x, warp = tid >> 5, lane = tid & 31;
    const int m0 = blockIdx.y * 128;
    const int n0g = n_base + blockIdx.x * 128;
    const int wm = (warp >> 2) * 64, wn = (warp & 3) * 32;

    const int cr = tid >> 3, cko = (tid & 7) * 8;
    const __nv_bfloat16* Ag = A + (size_t)(m0 + cr) * KCAT + cko;
    const __nv_bfloat16* Bg = Bm + (size_t)(n0g + cr) * KCAT + cko;
    const uint32_t sAo = (cr * AST + cko) * 2;

    float acc[4][4][4];
#pragma unroll
    for (int i = 0; i < 4; i++)
#pragma unroll
        for (int j = 0; j < 4; j++)
#pragma unroll
            for (int p = 0; p < 4; p++) acc[i][j][p] = 0.f;

#pragma unroll
    for (int i = 0; i < 4; i++) {
        cpasync16(sb + sAo + i * 32 * AST * 2, Ag + (size_t)(i * 32) * KCAT);
        cpasync16(sb + TILE_B + sAo + i * 32 * AST * 2, Bg + (size_t)(i * 32) * KCAT);
    }
    CP_COMMIT();

    const int NCH = KCAT / KC;
    for (int c = 0; c < NCH; c++) {
        const int p = c & 1;
        if (c + 1 < NCH) {
            const int pn = (c + 1) & 1;
            const size_t koff = (size_t)(c + 1) * KC;
#pragma unroll
            for (int i = 0; i < 4; i++) {
                cpasync16(sb + pn * 2 * TILE_B + sAo + i * 32 * AST * 2,
                          Ag + (size_t)(i * 32) * KCAT + koff);
                cpasync16(sb + pn * 2 * TILE_B + TILE_B + sAo + i * 32 * AST * 2,
                          Bg + (size_t)(i * 32) * KCAT + koff);
            }
            CP_COMMIT();
            CP_WAIT(1);
        } else {
            CP_WAIT(0);
        }
        __syncthreads();

        const uint32_t aw = sb + p * 2 * TILE_B +
                            ((wm + (lane & 15)) * AST + (lane >> 4) * 8) * 2;
        const uint32_t bw = sb + p * 2 * TILE_B + TILE_B +
                            ((wn + (lane & 15)) * AST + (lane >> 4) * 8) * 2;
#pragma unroll
        for (int k16 = 0; k16 < 4; k16++) {
            const uint32_t ko = k16 * 32;
            uint32_t a[4][4], b[8];
#pragma unroll
            for (int mt = 0; mt < 4; mt++)
                ldsm4(a[mt][0], a[mt][1], a[mt][2], a[mt][3],
                      aw + mt * 16 * AST * 2 + ko);
            ldsm4(b[0], b[1], b[2], b[3], bw + ko);
            ldsm4(b[4], b[5], b[6], b[7], bw + 16 * AST * 2 + ko);
#pragma unroll
            for (int mt = 0; mt < 4; mt++) {
                mma16816(acc[mt][0], a[mt][0], a[mt][1], a[mt][2], a[mt][3], b[0], b[2]);
                mma16816(acc[mt][1], a[mt][0], a[mt][1], a[mt][2], a[mt][3], b[1], b[3]);
                mma16816(acc[mt][2], a[mt][0], a[mt][1], a[mt][2], a[mt][3], b[4], b[6]);
                mma16816(acc[mt][3], a[mt][0], a[mt][1], a[mt][2], a[mt][3], b[5], b[7]);
            }
        }
        __syncthreads();
    }

#pragma unroll
    for (int nt = 0; nt < 4; nt++) {
        const int n = n0g + wn + nt * 8 + (lane & 3) * 2;
        const int wsel = n >> 10, nn = n & 1023;
        const float* bias = (wsel == 0) ? bq : (wsel == 1) ? bk : bv;
        __nv_bfloat16* ph = (wsel == 0) ? oQh : (wsel == 1) ? oKh : oVh;
        __nv_bfloat16* pl = (wsel == 0) ? oQl : (wsel == 1) ? oKl : oVl;
        const float b0 = bias[nn], b1 = bias[nn + 1];
        const size_t hoff = ((size_t)(nn >> 6)) * Slen;
        const int d = nn & 63;
#pragma unroll
        for (int mt = 0; mt < 4; mt++) {
#pragma unroll
            for (int half = 0; half < 2; half++) {
                const int r = m0 + wm + mt * 16 + (lane >> 2) + half * 8;
                const int bb = r >> msh, t = r - (bb << msh);
                float vx = acc[mt][nt][half * 2 + 0] + b0;
                float vy = acc[mt][nt][half * 2 + 1] + b1;
                __nv_bfloat16 hx = __float2bfloat16(vx);
                __nv_bfloat16 hy = __float2bfloat16(vy);
                float lxf = vx - __bfloat162float(hx);
                float lyf = vy - __bfloat162float(hy);
                size_t off = ((size_t)bb * NH * Slen + hoff + t) * DH + d;
                *(uint32_t*)(ph + off) =
                    (uint32_t)__bfloat16_as_ushort(hx) |
                    ((uint32_t)__bfloat16_as_ushort(hy) << 16);
                *(uint32_t*)(pl + off) = pk2(lxf, lyf);
            }
        }
    }
}

// ---------------------------------------------------------------------------
// Tensor-core attention.
// Block = 256 thr (8 warps), bh = blockIdx.y, l-tile 64 = blockIdx.x.
// Per r-tile: warps0-3 S_qk (3-term split); warps4-5 P1=Q@E^T; warps6-7
// P2=K@E^T; extract scores[l,r] = Sqk + P1[l,w] + P2[r,w], w=l-r+63; online
// softmax; P split hi/lo; all warps PV (3-term). 125KB smem, 1 CTA/SM.
// ---------------------------------------------------------------------------
#define PST 72
#define P12 136
#define A_SQH 0
#define A_SQL 9216
#define A_SKH 18432
#define A_SKL 27648
#define A_SVH 36864
#define A_SVL 46080
#define A_SEH 55296
#define A_SPH 73728
#define A_SPL 82944
#define A_SP1 92160
#define A_SP2 109568
#define A_CORR 126976
#define A_SSM 127232
#define A_SSI 127488
#define A_MSK 127744
#define A_TOTAL 128000

__device__ __forceinline__ void cp_tile64(char* sm, int dstoff,
                                          const __nv_bfloat16* src, int tid)
{
#pragma unroll
    for (int it = 0; it < 2; it++) {
        int i = tid + it * 256;
        int r = i >> 3, c = (i & 7) * 8;
        *(uint4*)(sm + dstoff + (r * PST + c) * 2) = *(const uint4*)(src + r * 64 + c);
    }
}
__device__ __forceinline__ float ldbf(const char* sm, int base, int idx) {
    return __bfloat162float(*(const __nv_bfloat16*)(sm + base + idx * 2));
}

__global__ __launch_bounds__(256, 1)
void attn_mma(const float* __restrict__ amask, const float* __restrict__ imask,
              const float* __restrict__ gate, float* __restrict__ outp)
{
    extern __shared__ char sm[];
    const uint32_t sb = smem_u32(sm);
    const int tid = threadIdx.x, warp = tid >> 5, lane = tid & 31;
    const int g = lane >> 2, t4 = lane & 3;
    const int bh = blockIdx.y, b = bh >> 4, h = bh & 15;
    const int l0 = blockIdx.x * 64;
    const int wm = warp * 16;                     // score warps 0-3
    const int wm2 = (warp >> 1) * 16, wn2 = (warp & 1) * 32;   // ctx frag

    // Q tiles (persistent)
    cp_tile64(sm, A_SQH, g_Qh + ((size_t)bh * SQ + l0) * DH, tid);
    cp_tile64(sm, A_SQL, g_Ql + ((size_t)bh * SQ + l0) * DH, tid);

    float cacc[4][4];
#pragma unroll
    for (int i = 0; i < 4; i++)
#pragma unroll
        for (int j = 0; j < 4; j++) cacc[i][j] = 0.f;
    float mrow[2] = {-1e30f, -1e30f}, ssum[2] = {0.f, 0.f};
    float* corr_sm = (float*)(sm + A_CORR);
    float* msk = (float*)(sm + A_MSK);

    // ======================= main pass =======================
    for (int rt = 0; rt < 16; rt++) {
        const int r0 = rt * 64;
        __syncthreads();
        cp_tile64(sm, A_SKH, g_Kh + ((size_t)bh * SQ + r0) * DH, tid);
        cp_tile64(sm, A_SKL, g_Kl + ((size_t)bh * SQ + r0) * DH, tid);
        cp_tile64(sm, A_SVH, g_Vh + ((size_t)bh * SQ + r0) * DH, tid);
        cp_tile64(sm, A_SVL, g_Vl + ((size_t)bh * SQ + r0) * DH, tid);
        {
            const __nv_bfloat16* Eg = g_Eh + (size_t)(l0 - r0 + 960) * 64;
#pragma unroll
            for (int it = 0; it < 4; it++) {
                int i = tid + it * 256;
                int r = i >> 3, c = (i & 7) * 8;
                *(uint4*)(sm + A_SEH + (r * PST + c) * 2) = *(const uint4*)(Eg + r * 64 + c);
            }
        }
        if (tid < 64) msk[tid] = amask[b * SQ + r0 + tid];
        __syncthreads();

        float sacc[8][4];
        if (warp < 4) {
#pragma unroll
            for (int j = 0; j < 8; j++)
#pragma unroll
                for (int p = 0; p < 4; p++) sacc[j][p] = 0.f;
#pragma unroll
            for (int k = 0; k < 4; k++) {
                const uint32_t ko = (k * 16 + (lane >> 4) * 8) * 2;
                uint32_t aH[4], aL[4];
                ldsm4(aH[0], aH[1], aH[2], aH[3],
                      sb + A_SQH + (wm + (lane & 15)) * PST * 2 + ko);
                ldsm4(aL[0], aL[1], aL[2], aL[3],
                      sb + A_SQL + (wm + (lane & 15)) * PST * 2 + ko);
#pragma unroll
                for (int nb = 0; nb < 4; nb++) {
                    uint32_t bH[4], bL[4];
                    ldsm4(bH[0], bH[1], bH[2], bH[3],
                          sb + A_SKH + (nb * 16 + (lane & 15)) * PST * 2 + ko);
                    ldsm4(bL[0], bL[1], bL[2], bL[3],
                          sb + A_SKL + (nb * 16 + (lane & 15)) * PST * 2 + ko);
                    mma16816(sacc[2 * nb], aH[0], aH[1], aH[2], aH[3], bH[0], bH[2]);
                    mma16816(sacc[2 * nb], aH[0], aH[1], aH[2], aH[3], bL[0], bL[2]);
                    mma16816(sacc[2 * nb], aL[0], aL[1], aL[2], aL[3], bH[0], bH[2]);
                    mma16816(sacc[2 * nb + 1], aH[0], aH[1], aH[2], aH[3], bH[1], bH[3]);
                    mma16816(sacc[2 * nb + 1], aH[0], aH[1], aH[2], aH[3], bL[1], bL[3]);
                    mma16816(sacc[2 * nb + 1], aL[0], aL[1], aL[2], aL[3], bH[1], bH[3]);
                }
            }
        } else {
            // P1 (warps 4,5) / P2 (warps 6,7): out[m][w] = M @ E^T, m rows 32/warp
            const int isP2 = (warp >= 6);
            const int m0p = (warp - (isP2 ? 6 : 4)) * 32;
            const int srcA = isP2 ? A_SKH : A_SQH;
            const int dstP = isP2 ? A_SP2 : A_SP1;
#pragma unroll
            for (int ch = 0; ch < 2; ch++) {
                float pacc[2][8][4];
#pragma unroll
                for (int s = 0; s < 2; s++)
#pragma unroll
                    for (int j = 0; j < 8; j++)
#pragma unroll
                        for (int p = 0; p < 4; p++) pacc[s][j][p] = 0.f;
#pragma unroll
                for (int k = 0; k < 4; k++) {
                    const uint32_t ko = (k * 16 + (lane >> 4) * 8) * 2;
                    uint32_t aU[4], aD[4];
                    ldsm4(aU[0], aU[1], aU[2], aU[3],
                          sb + srcA + (m0p + (lane & 15)) * PST * 2 + ko);
                    ldsm4(aD[0], aD[1], aD[2], aD[3],
                          sb + srcA + (m0p + 16 + (lane & 15)) * PST * 2 + ko);
#pragma unroll
                    for (int nb = 0; nb < 4; nb++) {
                        uint32_t be[4];
                        ldsm4(be[0], be[1], be[2], be[3],
                              sb + A_SEH + (ch * 64 + nb * 16 + (lane & 15)) * PST * 2 + ko);
                        mma16816(pacc[0][2 * nb], aU[0], aU[1], aU[2], aU[3], be[0], be[2]);
                        mma16816(pacc[0][2 * nb + 1], aU[0], aU[1], aU[2], aU[3], be[1], be[3]);
                        mma16816(pacc[1][2 * nb], aD[0], aD[1], aD[2], aD[3], be[0], be[2]);
                        mma16816(pacc[1][2 * nb + 1], aD[0], aD[1], aD[2], aD[3], be[1], be[3]);
                    }
                }
#pragma unroll
                for (int s = 0; s < 2; s++)
#pragma unroll
                    for (int j = 0; j < 8; j++) {
                        int l = m0p + s * 16 + g;
                        int w = ch * 64 + 8 * j + 2 * t4;
                        *(uint32_t*)(sm + dstP + (l * P12 + w) * 2) =
                            pk2(pacc[s][j][0], pacc[s][j][1]);
                        *(uint32_t*)(sm + dstP + ((l + 8) * P12 + w) * 2) =
                            pk2(pacc[s][j][2], pacc[s][j][3]);
                    }
            }
        }
        __syncthreads();

        if (warp < 4) {
            const int l = wm + g;
#pragma unroll
            for (int j = 0; j < 8; j++) {
                const int r = 8 * j + 2 * t4;
                const int w = l - r + 63;
                sacc[j][0] = (sacc[j][0] + ldbf(sm, A_SP1, l * P12 + w)
                              + ldbf(sm, A_SP2, r * P12 + w)) * 0.125f + msk[r];
                sacc[j][1] = (sacc[j][1] + ldbf(sm, A_SP1, l * P12 + w - 1)
                              + ldbf(sm, A_SP2, (r + 1) * P12 + w - 1)) * 0.125f + msk[r + 1];
                sacc[j][2] = (sacc[j][2] + ldbf(sm, A_SP1, (l + 8) * P12 + w + 8)
                              + ldbf(sm, A_SP2, r * P12 + w + 8)) * 0.125f + msk[r];
                sacc[j][3] = (sacc[j][3] + ldbf(sm, A_SP1, (l + 8) * P12 + w + 7)
                              + ldbf(sm, A_SP2, (r + 1) * P12 + w + 7)) * 0.125f + msk[r + 1];
            }
            float mt0 = -1e30f, mt1 = -1e30f;
#pragma unroll
            for (int j = 0; j < 8; j++) {
                mt0 = fmaxf(mt0, fmaxf(sacc[j][0], sacc[j][1]));
                mt1 = fmaxf(mt1, fmaxf(sacc[j][2], sacc[j][3]));
            }
            mt0 = fmaxf(mt0, __shfl_xor_sync(0xffffffffu, mt0, 1));
            mt0 = fmaxf(mt0, __shfl_xor_sync(0xffffffffu, mt0, 2));
            mt1 = fmaxf(mt1, __shfl_xor_sync(0xffffffffu, mt1, 1));
            mt1 = fmaxf(mt1, __shfl_xor_sync(0xffffffffu, mt1, 2));
            float mn0 = fmaxf(mrow[0], mt0), mn1 = fmaxf(mrow[1], mt1);
            float cr0 = __expf(mrow[0] - mn0), cr1 = __expf(mrow[1] - mn1);
            mrow[0] = mn0; mrow[1] = mn1;
            float ps0 = 0.f, ps1 = 0.f;
#pragma unroll
            for (int j = 0; j < 8; j++) {
                float p00 = __expf(sacc[j][0] - mn0), p01 = __expf(sacc[j][1] - mn0);
                float p10 = __expf(sacc[j][2] - mn1), p11 = __expf(sacc[j][3] - mn1);
                ps0 += p00 + p01; ps1 += p10 + p11;
                int cidx = 8 * j + 2 * t4;
                uint32_t h0 = pk2(p00, p01), h1 = pk2(p10, p11);
                *(uint32_t*)(sm + A_SPH + (l * PST + cidx) * 2) = h0;
                *(uint32_t*)(sm + A_SPH + ((l + 8) * PST + cidx) * 2) = h1;
                __nv_bfloat162 hh0 = *(__nv_bfloat162*)&h0;
                __nv_bfloat162 hh1 = *(__nv_bfloat162*)&h1;
                *(uint32_t*)(sm + A_SPL + (l * PST + cidx) * 2) =
                    pk2(p00 - __bfloat162float(hh0.x), p01 - __bfloat162float(hh0.y));
                *(uint32_t*)(sm + A_SPL + ((l + 8) * PST + cidx) * 2) =
                    pk2(p10 - __bfloat162float(hh1.x), p11 - __bfloat162float(hh1.y));
            }
            ps0 += __shfl_xor_sync(0xffffffffu, ps0, 1);
            ps0 += __shfl_xor_sync(0xffffffffu, ps0, 2);
            ps1 += __shfl_xor_sync(0xffffffffu, ps1, 1);
            ps1 += __shfl_xor_sync(0xffffffffu, ps1, 2);
            ssum[0] = ssum[0] * cr0 + ps0;
            ssum[1] = ssum[1] * cr1 + ps1;
            if (t4 == 0) { corr_sm[l] = cr0; corr_sm[l + 8] = cr1; }
        }
        __syncthreads();

        // PV (all warps)
        {
            float c0r = corr_sm[wm2 + g], c1r = corr_sm[wm2 + 8 + g];
#pragma unroll
            for (int nf = 0; nf < 4; nf++) {
                cacc[nf][0] *= c0r; cacc[nf][1] *= c0r;
                cacc[nf][2] *= c1r; cacc[nf][3] *= c1r;
            }
#pragma unroll
            for (int kk = 0; kk < 4; kk++) {
                const uint32_t ko = (kk * 16 + (lane >> 4) * 8) * 2;
                uint32_t aPh[4], aPl[4];
                ldsm4(aPh[0], aPh[1], aPh[2], aPh[3],
                      sb + A_SPH + (wm2 + (lane & 15)) * PST * 2 + ko);
                ldsm4(aPl[0], aPl[1], aPl[2], aPl[3],
                      sb + A_SPL + (wm2 + (lane & 15)) * PST * 2 + ko);
#pragma unroll
                for (int dh = 0; dh < 2; dh++) {
                    const uint32_t trow = (kk * 16 + (lane & 7) + 8 * ((lane >> 3) & 1)) * PST;
                    const uint32_t tcol = wn2 + dh * 16 + ((lane >> 4) & 1) * 8;
                    uint32_t bh2[4], bl2[4];
                    ldsm4t(bh2[0], bh2[1], bh2[2], bh2[3], sb + A_SVH + (trow + tcol) * 2);
                    ldsm4t(bl2[0], bl2[1], bl2[2], bl2[3], sb + A_SVL + (trow + tcol) * 2);
                    const int nf = dh * 2;
                    mma16816(cacc[nf], aPh[0], aPh[1], aPh[2], aPh[3], bh2[0], bh2[1]);
                    mma16816(cacc[nf], aPh[0], aPh[1], aPh[2], aPh[3], bl2[0], bl2[1]);
                    mma16816(cacc[nf], aPl[0], aPl[1], aPl[2], aPl[3], bh2[0], bh2[1]);
                    mma16816(cacc[nf + 1], aPh[0], aPh[1], aPh[2], aPh[3], bh2[2], bh2[3]);
                    mma16816(cacc[nf + 1], aPh[0], aPh[1], aPh[2], aPh[3], bl2[2], bl2[3]);
                    mma16816(cacc[nf + 1], aPl[0], aPl[1], aPl[2], aPl[3], bh2[2], bh2[3]);
                }
            }
        }
    }

    // stash main ctx + ssum, reset
    __syncthreads();
    {
        float* stash = (float*)(sm + A_SP1);
#pragma unroll
        for (int nf = 0; nf < 4; nf++) {
            int d = wn2 + 8 * nf + 2 * t4;
            stash[(wm2 + g) * 68 + d] = cacc[nf][0];
            stash[(wm2 + g) * 68 + d + 1] = cacc[nf][1];
            stash[(wm2 + 8 + g) * 68 + d] = cacc[nf][2];
            stash[(wm2 + 8 + g) * 68 + d + 1] = cacc[nf][3];
            cacc[nf][0] = cacc[nf][1] = cacc[nf][2] = cacc[nf][3] = 0.f;
        }
        if (warp < 4 && t4 == 0) {
            ((float*)(sm + A_SSM))[wm + g] = ssum[0];
            ((float*)(sm + A_SSM))[wm + g + 8] = ssum[1];
        }
        mrow[0] = mrow[1] = -1e30f; ssum[0] = ssum[1] = 0.f;
    }

    // ======================= instruct pass =======================
    for (int rt = 0; rt < 2; rt++) {
        const int r0 = rt * 64;
        __syncthreads();
        cp_tile64(sm, A_SKH, g_IKh + ((size_t)bh * LI + r0) * DH, tid);
        cp_tile64(sm, A_SKL, g_IKl + ((size_t)bh * LI + r0) * DH, tid);
        cp_tile64(sm, A_SVH, g_IVh + ((size_t)bh * LI + r0) * DH, tid);
        cp_tile64(sm, A_SVL, g_IVl + ((size_t)bh * LI + r0) * DH, tid);
        if (tid < 64) msk[tid] = imask[b * LI + r0 + tid];
        __syncthreads();

        if (warp < 4) {
            float sacc[8][4];
#pragma unroll
            for (int j = 0; j < 8; j++)
#pragma unroll
                for (int p = 0; p < 4; p++) sacc[j][p] = 0.f;
#pragma unroll
            for (int k = 0; k < 4; k++) {
                const uint32_t ko = (k * 16 + (lane >> 4) * 8) * 2;
                uint32_t aH[4], aL[4];
                ldsm4(aH[0], aH[1], aH[2], aH[3],
                      sb + A_SQH + (wm + (lane & 15)) * PST * 2 + ko);
                ldsm4(aL[0], aL[1], aL[2], aL[3],
                      sb + A_SQL + (wm + (lane & 15)) * PST * 2 + ko);
#pragma unroll
                for (int nb = 0; nb < 4; nb++) {
                    uint32_t bH[4], bL[4];
                    ldsm4(bH[0], bH[1], bH[2], bH[3],
                          sb + A_SKH + (nb * 16 + (lane & 15)) * PST * 2 + ko);
                    ldsm4(bL[0], bL[1], bL[2], bL[3],
                          sb + A_SKL + (nb * 16 + (lane & 15)) * PST * 2 + ko);
                    mma16816(sacc[2 * nb], aH[0], aH[1], aH[2], aH[3], bH[0], bH[2]);
                    mma16816(sacc[2 * nb], aH[0], aH[1], aH[2], aH[3], bL[0], bL[2]);
                    mma16816(sacc[2 * nb], aL[0], aL[1], aL[2], aL[3], bH[0], bH[2]);
                    mma16816(sacc[2 * nb + 1], aH[0], aH[1], aH[2], aH[3], bH[1], bH[3]);
                    mma16816(sacc[2 * nb + 1], aH[0], aH[1], aH[2], aH[3], bL[1], bL[3]);
                    mma16816(sacc[2 * nb + 1], aL[0], aL[1], aL[2], aL[3], bH[1], bH[3]);
                }
            }
            const int l = wm + g;
            float mt0 = -1e30f, mt1 = -1e30f;
#pragma unroll
            for (int j = 0; j < 8; j++) {
                const int r = 8 * j + 2 * t4;
                sacc[j][0] = sacc[j][0] * 0.125f + msk[r];
                sacc[j][1] = sacc[j][1] * 0.125f + msk[r + 1];
                sacc[j][2] = sacc[j][2] * 0.125f + msk[r];
                sacc[j][3] = sacc[j][3] * 0.125f + msk[r + 1];
                mt0 = fmaxf(mt0, fmaxf(sacc[j][0], sacc[j][1]));
                mt1 = fmaxf(mt1, fmaxf(sacc[j][2], sacc[j][3]));
            }
            mt0 = fmaxf(mt0, __shfl_xor_sync(0xffffffffu, mt0, 1));
            mt0 = fmaxf(mt0, __shfl_xor_sync(0xffffffffu, mt0, 2));
            mt1 = fmaxf(mt1, __shfl_xor_sync(0xffffffffu, mt1, 1));
            mt1 = fmaxf(mt1, __shfl_xor_sync(0xffffffffu, mt1, 2));
            float mn0 = fmaxf(mrow[0], mt0), mn1 = fmaxf(mrow[1], mt1);
            float cr0 = __expf(mrow[0] - mn0), cr1 = __expf(mrow[1] - mn1);
            mrow[0] = mn0; mrow[1] = mn1;
            float ps0 = 0.f, ps1 = 0.f;
#pragma unroll
            for (int j = 0; j < 8; j++) {
                float p00 = __expf(sacc[j][0] - mn0), p01 = __expf(sacc[j][1] - mn0);
                float p10 = __expf(sacc[j][2] - mn1), p11 = __expf(sacc[j][3] - mn1);
                ps0 += p00 + p01; ps1 += p10 + p11;
                int cidx = 8 * j + 2 * t4;
                uint32_t h0 = pk2(p00, p01), h1 = pk2(p10, p11);
                *(uint32_t*)(sm + A_SPH + (l * PST + cidx) * 2) = h0;
                *(uint32_t*)(sm + A_SPH + ((l + 8) * PST + cidx) * 2) = h1;
                __nv_bfloat162 hh0 = *(__nv_bfloat162*)&h0;
                __nv_bfloat162 hh1 = *(__nv_bfloat162*)&h1;
                *(uint32_t*)(sm + A_SPL + (l * PST + cidx) * 2) =
                    pk2(p00 - __bfloat162float(hh0.x), p01 - __bfloat162float(hh0.y));
                *(uint32_t*)(sm + A_SPL + ((l + 8) * PST + cidx) * 2) =
                    pk2(p10 - __bfloat162float(hh1.x), p11 - __bfloat162float(hh1.y));
            }
            ps0 += __shfl_xor_sync(0xffffffffu, ps0, 1);
            ps0 += __shfl_xor_sync(0xffffffffu, ps0, 2);
            ps1 += __shfl_xor_sync(0xffffffffu, ps1, 1);
            ps1 += __shfl_xor_sync(0xffffffffu, ps1, 2);
            ssum[0] = ssum[0] * cr0 + ps0;
            ssum[1] = ssum[1] * cr1 + ps1;
            if (t4 == 0) { corr_sm[l] = cr0; corr_sm[l + 8] = cr1; }
        }
        __syncthreads();

        {
            float c0r = corr_sm[wm2 + g], c1r = corr_sm[wm2 + 8 + g];
#pragma unroll
            for (int nf = 0; nf < 4; nf++) {
                cacc[nf][0] *= c0r; cacc[nf][1] *= c0r;
                cacc[nf][2] *= c1r; cacc[nf][3] *= c1r;
            }
#pragma unroll
            for (int kk = 0; kk < 4; kk++) {
                const uint32_t ko = (kk * 16 + (lane >> 4) * 8) * 2;
                uint32_t aPh[4], aPl[4];
                ldsm4(aPh[0], aPh[1], aPh[2], aPh[3],
                      sb + A_SPH + (wm2 + (lane & 15)) * PST * 2 + ko);
                ldsm4(aPl[0], aPl[1], aPl[2], aPl[3],
                      sb + A_SPL + (wm2 + (lane & 15)) * PST * 2 + ko);
#pragma unroll
                for (int dh = 0; dh < 2; dh++) {
                    const uint32_t trow = (kk * 16 + (lane & 7) + 8 * ((lane >> 3) & 1)) * PST;
                    const uint32_t tcol = wn2 + dh * 16 + ((lane >> 4) & 1) * 8;
                    uint32_t bh2[4], bl2[4];
                    ldsm4t(bh2[0], bh2[1], bh2[2], bh2[3], sb + A_SVH + (trow + tcol) * 2);
                    ldsm4t(bl2[0], bl2[1], bl2[2], bl2[3], sb + A_SVL + (trow + tcol) * 2);
                    const int nf = dh * 2;
                    mma16816(cacc[nf], aPh[0], aPh[1], aPh[2], aPh[3], bh2[0], bh2[1]);
                    mma16816(cacc[nf], aPh[0], aPh[1], aPh[2], aPh[3], bl2[0], bl2[1]);
                    mma16816(cacc[nf], aPl[0], aPl[1], aPl[2], aPl[3], bh2[0], bh2[1]);
                    mma16816(cacc[nf + 1], aPh[0], aPh[1], aPh[2], aPh[3], bh2[2], bh2[3]);
                    mma16816(cacc[nf + 1], aPh[0], aPh[1], aPh[2], aPh[3], bl2[2], bl2[3]);
                    mma16816(cacc[nf + 1], aPl[0], aPl[1], aPl[2], aPl[3], bh2[2], bh2[3]);
                }
            }
        }
    }

    __syncthreads();
    if (warp < 4 && t4 == 0) {
        ((float*)(sm + A_SSI))[wm + g] = ssum[0];
        ((float*)(sm + A_SSI))[wm + g + 8] = ssum[1];
    }
    __syncthreads();

    // epilogue
    {
        const float tg = tanhf(gate[h]);
        const float* stash = (const float*)(sm + A_SP1);
        const float* ssm = (const float*)(sm + A_SSM);
        const float* ssi = (const float*)(sm + A_SSI);
        const float rnm0 = 1.f / ssm[wm2 + g], rni0 = tg / ssi[wm2 + g];
        const float rnm1 = 1.f / ssm[wm2 + 8 + g], rni1 = tg / ssi[wm2 + 8 + g];
#pragma unroll
        for (int nf = 0; nf < 4; nf++) {
            const int d = wn2 + 8 * nf + 2 * t4;
            float2 o0, o1;
            o0.x = stash[(wm2 + g) * 68 + d] * rnm0 + cacc[nf][0] * rni0;
            o0.y = stash[(wm2 + g) * 68 + d + 1] * rnm0 + cacc[nf][1] * rni0;
            o1.x = stash[(wm2 + 8 + g) * 68 + d] * rnm1 + cacc[nf][2] * rni1;
            o1.y = stash[(wm2 + 8 + g) * 68 + d + 1] * rnm1 + cacc[nf][3] * rni1;
            *(float2*)(outp + ((size_t)(b * SQ + l0 + wm2 + g)) * HIDDEN + h * DH + d) = o0;
            *(float2*)(outp + ((size_t)(b * SQ + l0 + wm2 + 8 + g)) * HIDDEN + h * DH + d) = o1;
        }
    }
}

// ---------------------------------------------------------------------------
extern "C" void kernel_launch(void* const* d_in, const int* in_sizes, int n_in,
                              void* d_out, int out_size)
{
    (void)in_sizes; (void)n_in; (void)out_size;
    const float* hs    = (const float*)d_in[0];
    const float* amask = (const float*)d_in[1];
    const float* ihs   = (const float*)d_in[2];
    const float* imask = (const float*)d_in[3];
    const float* Wq    = (const float*)d_in[4];
    const float* bq    = (const float*)d_in[5];
    const float* Wk    = (const float*)d_in[6];
    const float* bk    = (const float*)d_in[7];
    const float* Wv    = (const float*)d_in[8];
    const float* bv    = (const float*)d_in[9];
    const float* gate  = (const float*)d_in[10];
    const float* dist  = (const float*)d_in[11];
    float* out = (float*)d_out;

    __nv_bfloat16 *qh, *ql, *kh, *kl, *vh, *vl, *ikh, *ikl, *ivh, *ivl, *eh;
    __nv_bfloat16 *xc, *ixc, *wc;
    cudaGetSymbolAddress((void**)&qh, g_Qh);
    cudaGetSymbolAddress((void**)&ql, g_Ql);
    cudaGetSymbolAddress((void**)&kh, g_Kh);
    cudaGetSymbolAddress((void**)&kl, g_Kl);
    cudaGetSymbolAddress((void**)&vh, g_Vh);
    cudaGetSymbolAddress((void**)&vl, g_Vl);
    cudaGetSymbolAddress((void**)&ikh, g_IKh);
    cudaGetSymbolAddress((void**)&ikl, g_IKl);
    cudaGetSymbolAddress((void**)&ivh, g_IVh);
    cudaGetSymbolAddress((void**)&ivl, g_IVl);
    cudaGetSymbolAddress((void**)&eh, g_Eh);
    cudaGetSymbolAddress((void**)&xc, g_Xcat);
    cudaGetSymbolAddress((void**)&ixc, g_IXcat);
    cudaGetSymbolAddress((void**)&wc, g_Wcat);

    cudaFuncSetAttribute(gemm_mma, cudaFuncAttributeMaxDynamicSharedMemorySize, GEMM_SMEM);
    cudaFuncSetAttribute(attn_mma, cudaFuncAttributeMaxDynamicSharedMemorySize, A_TOTAL);

    conv_x<<<(NB * SQ * HIDDEN / 4 + 255) / 256, 256>>>((const float4*)hs, xc,
                                                        NB * SQ * HIDDEN / 4);
    conv_x<<<(NB * LI * HIDDEN / 4 + 255) / 256, 256>>>((const float4*)ihs, ixc,
                                                        NB * LI * HIDDEN / 4);
    conv_w<<<dim3(32, 32, 3), 256>>>(Wq, Wk, Wv, wc);
    conv_e<<<(2048 * 64 + 255) / 256, 256>>>(dist, eh);

    gemm_mma<<<dim3(24, 32), 256, GEMM_SMEM>>>(xc, 10, SQ, wc, bq, bk, bv,
                                               qh, ql, kh, kl, vh, vl, 0);
    gemm_mma<<<dim3(16, 4), 256, GEMM_SMEM>>>(ixc, 7, LI, wc, bq, bk, bv,
                                              qh, ql, ikh, ikl, ivh, ivl, 1024);

    attn_mma<<<dim3(SQ / 64, BHN), 256, A_TOTAL>>>(amask, imask, gate, out);
}

// round 6
// speedup vs baseline: 4.3035x; 1.0116x over previous
#include <cuda_runtime.h>
#include <cuda_bf16.h>
#include <math.h>
#include <cstdint>

#define NB 4
#define NH 16
#define DH 64
#define SQ 1024
#define LI 128
#define HIDDEN 1024
#define BHN (NB * NH)
#define KW 2048   // stored operand width (hi|lo)

// ---------------- scratch ---------------------------------------------------
__device__ __align__(16) __nv_bfloat16 g_Qh[BHN * SQ * DH];
__device__ __align__(16) __nv_bfloat16 g_Ql[BHN * SQ * DH];
__device__ __align__(16) __nv_bfloat16 g_Kh[BHN * SQ * DH];
__device__ __align__(16) __nv_bfloat16 g_Kl[BHN * SQ * DH];
__device__ __align__(16) __nv_bfloat16 g_Vh[BHN * SQ * DH];
__device__ __align__(16) __nv_bfloat16 g_Vl[BHN * SQ * DH];
__device__ __align__(16) __nv_bfloat16 g_IKh[BHN * LI * DH];
__device__ __align__(16) __nv_bfloat16 g_IKl[BHN * LI * DH];
__device__ __align__(16) __nv_bfloat16 g_IVh[BHN * LI * DH];
__device__ __align__(16) __nv_bfloat16 g_IVl[BHN * LI * DH];
__device__ __align__(16) __nv_bfloat16 g_Eh[2048 * DH];

__device__ __align__(16) __nv_bfloat16 g_Xcat[NB * SQ * KW];
__device__ __align__(16) __nv_bfloat16 g_IXcat[NB * LI * KW];
__device__ __align__(16) __nv_bfloat16 g_Wcat[3 * HIDDEN * KW];

// ---------------- helpers ---------------------------------------------------
__device__ __forceinline__ uint32_t smem_u32(const void* p) {
    uint32_t a;
    asm("{ .reg .u64 t; cvta.to.shared.u64 t, %1; cvt.u32.u64 %0, t; }" : "=r"(a) : "l"(p));
    return a;
}
__device__ __forceinline__ void ldsm4(uint32_t& r0, uint32_t& r1, uint32_t& r2,
                                      uint32_t& r3, uint32_t addr) {
    asm volatile("ldmatrix.sync.aligned.m8n8.x4.shared.b16 {%0,%1,%2,%3}, [%4];"
                 : "=r"(r0), "=r"(r1), "=r"(r2), "=r"(r3) : "r"(addr));
}
__device__ __forceinline__ void ldsm4t(uint32_t& r0, uint32_t& r1, uint32_t& r2,
                                       uint32_t& r3, uint32_t addr) {
    asm volatile("ldmatrix.sync.aligned.m8n8.x4.trans.shared.b16 {%0,%1,%2,%3}, [%4];"
                 : "=r"(r0), "=r"(r1), "=r"(r2), "=r"(r3) : "r"(addr));
}
__device__ __forceinline__ void mma16816(float* c, uint32_t a0, uint32_t a1,
                                         uint32_t a2, uint32_t a3,
                                         uint32_t b0, uint32_t b1) {
    asm volatile(
        "mma.sync.aligned.m16n8k16.row.col.f32.bf16.bf16.f32 "
        "{%0,%1,%2,%3}, {%4,%5,%6,%7}, {%8,%9}, {%0,%1,%2,%3};"
        : "+f"(c[0]), "+f"(c[1]), "+f"(c[2]), "+f"(c[3])
        : "r"(a0), "r"(a1), "r"(a2), "r"(a3), "r"(b0), "r"(b1));
}
__device__ __forceinline__ uint32_t pk2(float a, float b) {
    __nv_bfloat162 t = __floats2bfloat162_rn(a, b);
    return *(uint32_t*)&t;
}
__device__ __forceinline__ void cpasync16(uint32_t dst, const void* src) {
    asm volatile("cp.async.cg.shared.global [%0], [%1], 16;" :: "r"(dst), "l"(src));
}
#define CP_COMMIT() asm volatile("cp.async.commit_group;" ::: "memory")
#define CP_WAIT(n)  asm volatile("cp.async.wait_group %0;" :: "n"(n) : "memory")

// ---------------------------------------------------------------------------
// Conversions
// ---------------------------------------------------------------------------
__global__ __launch_bounds__(256)
void conv_x(const float4* __restrict__ src, __nv_bfloat16* __restrict__ dst, int n4)
{
    int i = blockIdx.x * 256 + threadIdx.x;
    if (i >= n4) return;
    int row = i >> 8, c4 = (i & 255) * 4;
    float4 v = src[i];
    __nv_bfloat16 hx = __float2bfloat16(v.x), hy = __float2bfloat16(v.y);
    __nv_bfloat16 hz = __float2bfloat16(v.z), hw = __float2bfloat16(v.w);
    __nv_bfloat16 lx = __float2bfloat16(v.x - __bfloat162float(hx));
    __nv_bfloat16 ly = __float2bfloat16(v.y - __bfloat162float(hy));
    __nv_bfloat16 lz = __float2bfloat16(v.z - __bfloat162float(hz));
    __nv_bfloat16 lw = __float2bfloat16(v.w - __bfloat162float(hw));
    uint2 H, L;
    H.x = (uint32_t)__bfloat16_as_ushort(hx) | ((uint32_t)__bfloat16_as_ushort(hy) << 16);
    H.y = (uint32_t)__bfloat16_as_ushort(hz) | ((uint32_t)__bfloat16_as_ushort(hw) << 16);
    L.x = (uint32_t)__bfloat16_as_ushort(lx) | ((uint32_t)__bfloat16_as_ushort(ly) << 16);
    L.y = (uint32_t)__bfloat16_as_ushort(lz) | ((uint32_t)__bfloat16_as_ushort(lw) << 16);
    __nv_bfloat16* rb = dst + (size_t)row * KW + c4;
    *(uint2*)(rb)        = H;
    *(uint2*)(rb + 1024) = L;
}

__global__ __launch_bounds__(256)
void conv_w(const float* __restrict__ Wq, const float* __restrict__ Wk,
            const float* __restrict__ Wv, __nv_bfloat16* __restrict__ dst)
{
    const float* W = (blockIdx.z == 0) ? Wq : (blockIdx.z == 1) ? Wk : Wv;
    __shared__ float t[32][33];
    int tx = threadIdx.x & 31, ty = threadIdx.x >> 5;
    int n = blockIdx.x * 32 + tx, k0 = blockIdx.y * 32;
#pragma unroll
    for (int j = 0; j < 4; j++)
        t[ty + 8 * j][tx] = W[(size_t)(k0 + ty + 8 * j) * HIDDEN + n];
    __syncthreads();
    size_t nrow = (size_t)blockIdx.z * HIDDEN + blockIdx.x * 32;
#pragma unroll
    for (int j = 0; j < 4; j++) {
        float v = t[tx][ty + 8 * j];
        __nv_bfloat16 h = __float2bfloat16(v);
        __nv_bfloat16 l = __float2bfloat16(v - __bfloat162float(h));
        __nv_bfloat16* o = dst + (nrow + ty + 8 * j) * KW + k0 + tx;
        o[0]    = h;
        o[1024] = l;
    }
}

__global__ __launch_bounds__(256)
void conv_e(const float* __restrict__ dist, __nv_bfloat16* __restrict__ eh)
{
    int i = blockIdx.x * 256 + threadIdx.x;
    if (i >= 2048 * 64) return;
    float v = (i < 2047 * 64) ? dist[i] : 0.f;
    eh[i] = __float2bfloat16(v);
}

// ---------------------------------------------------------------------------
// Projection GEMM: virtual K'=3072 (3-term split) from 2048-wide stores.
// ---------------------------------------------------------------------------
#define KC 64
#define AST 72
#define TILE_B (128 * AST * 2)
#define GEMM_SMEM (4 * TILE_B)

__global__ __launch_bounds__(256, 2)
void gemm_mma(const __nv_bfloat16* __restrict__ A, int msh, int Slen,
              const __nv_bfloat16* __restrict__ Bm,
              const float* __restrict__ bq, const float* __restrict__ bk,
              const float* __restrict__ bv,
              __nv_bfloat16* oQh, __nv_bfloat16* oQl,
              __nv_bfloat16* oKh, __nv_bfloat16* oKl,
              __nv_bfloat16* oVh, __nv_bfloat16* oVl, int n_base)
{
    extern __shared__ char smem[];
    const uint32_t sb = smem_u32(smem);
    const int tid = threadIdx.x, warp = tid >> 5, lane = tid & 31;
    const int m0 = blockIdx.y * 128;
    const int n0g = n_base + blockIdx.x * 128;
    const int wm = (warp >> 2) * 64, wn = (warp & 3) * 32;

    const int cr = tid >> 3, cko = (tid & 7) * 8;
    const __nv_bfloat16* Ag = A + (size_t)(m0 + cr) * KW + cko;
    const __nv_bfloat16* Bg = Bm + (size_t)(n0g + cr) * KW + cko;
    const uint32_t sAo = (cr * AST + cko) * 2;

    float acc[4][4][4];
#pragma unroll
    for (int i = 0; i < 4; i++)
#pragma unroll
        for (int j = 0; j < 4; j++)
#pragma unroll
            for (int p = 0; p < 4; p++) acc[i][j][p] = 0.f;

#pragma unroll
    for (int i = 0; i < 4; i++) {
        cpasync16(sb + sAo + i * 32 * AST * 2, Ag + (size_t)(i * 32) * KW);
        cpasync16(sb + TILE_B + sAo + i * 32 * AST * 2, Bg + (size_t)(i * 32) * KW);
    }
    CP_COMMIT();

    const int NCH = 48;
    for (int c = 0; c < NCH; c++) {
        const int p = c & 1;
        if (c + 1 < NCH) {
            const int pn = (c + 1) & 1;
            const int cn = c + 1;
            const int aoff = (cn < 16) ? cn * 64 : cn * 64 - 1024;
            const int boff = (cn < 32) ? cn * 64 : cn * 64 - 2048;
#pragma unroll
            for (int i = 0; i < 4; i++) {
                cpasync16(sb + pn * 2 * TILE_B + sAo + i * 32 * AST * 2,
                          Ag + (size_t)(i * 32) * KW + aoff);
                cpasync16(sb + pn * 2 * TILE_B + TILE_B + sAo + i * 32 * AST * 2,
                          Bg + (size_t)(i * 32) * KW + boff);
            }
            CP_COMMIT();
            CP_WAIT(1);
        } else {
            CP_WAIT(0);
        }
        __syncthreads();

        const uint32_t aw = sb + p * 2 * TILE_B +
                            ((wm + (lane & 15)) * AST + (lane >> 4) * 8) * 2;
        const uint32_t bw = sb + p * 2 * TILE_B + TILE_B +
                            ((wn + (lane & 15)) * AST + (lane >> 4) * 8) * 2;
#pragma unroll
        for (int k16 = 0; k16 < 4; k16++) {
            const uint32_t ko = k16 * 32;
            uint32_t a[4][4], b[8];
#pragma unroll
            for (int mt = 0; mt < 4; mt++)
                ldsm4(a[mt][0], a[mt][1], a[mt][2], a[mt][3],
                      aw + mt * 16 * AST * 2 + ko);
            ldsm4(b[0], b[1], b[2], b[3], bw + ko);
            ldsm4(b[4], b[5], b[6], b[7], bw + 16 * AST * 2 + ko);
#pragma unroll
            for (int mt = 0; mt < 4; mt++) {
                mma16816(acc[mt][0], a[mt][0], a[mt][1], a[mt][2], a[mt][3], b[0], b[2]);
                mma16816(acc[mt][1], a[mt][0], a[mt][1], a[mt][2], a[mt][3], b[1], b[3]);
                mma16816(acc[mt][2], a[mt][0], a[mt][1], a[mt][2], a[mt][3], b[4], b[6]);
                mma16816(acc[mt][3], a[mt][0], a[mt][1], a[mt][2], a[mt][3], b[5], b[7]);
            }
        }
        __syncthreads();
    }

#pragma unroll
    for (int nt = 0; nt < 4; nt++) {
        const int n = n0g + wn + nt * 8 + (lane & 3) * 2;
        const int wsel = n >> 10, nn = n & 1023;
        const float* bias = (wsel == 0) ? bq : (wsel == 1) ? bk : bv;
        __nv_bfloat16* ph = (wsel == 0) ? oQh : (wsel == 1) ? oKh : oVh;
        __nv_bfloat16* pl = (wsel == 0) ? oQl : (wsel == 1) ? oKl : oVl;
        const float b0 = bias[nn], b1 = bias[nn + 1];
        const size_t hoff = ((size_t)(nn >> 6)) * Slen;
        const int d = nn & 63;
#pragma unroll
        for (int mt = 0; mt < 4; mt++) {
#pragma unroll
            for (int half = 0; half < 2; half++) {
                const int r = m0 + wm + mt * 16 + (lane >> 2) + half * 8;
                const int bb = r >> msh, t = r - (bb << msh);
                float vx = acc[mt][nt][half * 2 + 0] + b0;
                float vy = acc[mt][nt][half * 2 + 1] + b1;
                __nv_bfloat16 hx = __float2bfloat16(vx);
                __nv_bfloat16 hy = __float2bfloat16(vy);
                float lxf = vx - __bfloat162float(hx);
                float lyf = vy - __bfloat162float(hy);
                size_t off = ((size_t)bb * NH * Slen + hoff + t) * DH + d;
                *(uint32_t*)(ph + off) =
                    (uint32_t)__bfloat16_as_ushort(hx) |
                    ((uint32_t)__bfloat16_as_ushort(hy) << 16);
                *(uint32_t*)(pl + off) = pk2(lxf, lyf);
            }
        }
    }
}

// ---------------------------------------------------------------------------
// Tensor-core attention with double-buffered cp.async K/V/E pipeline.
// ---------------------------------------------------------------------------
#define PST 72
#define P12 136
#define A_SQH 0
#define A_SQL 9216
#define A_KV0 18432
#define KVSET 36864
#define KOH 0
#define KOL 9216
#define VOH 18432
#define VOL 27648
#define A_E0 92160
#define ESET 18432
#define A_SPH 129024
#define A_SPL 138240
#define A_SP1 147456
#define A_SP2 164864
#define A_CORR 182272
#define A_SSM 182528
#define A_SSI 182784
#define A_MSK 183040
#define A_TOTAL 183296

__device__ __forceinline__ void cp_tile64(char* sm, int dstoff,
                                          const __nv_bfloat16* src, int tid)
{
#pragma unroll
    for (int it = 0; it < 2; it++) {
        int i = tid + it * 256;
        int r = i >> 3, c = (i & 7) * 8;
        *(uint4*)(sm + dstoff + (r * PST + c) * 2) = *(const uint4*)(src + r * 64 + c);
    }
}
__device__ __forceinline__ void cpa_tile64(uint32_t sb, int dstoff,
                                           const __nv_bfloat16* src, int tid)
{
#pragma unroll
    for (int it = 0; it < 2; it++) {
        int i = tid + it * 256;
        int r = i >> 3, c = (i & 7) * 8;
        cpasync16(sb + dstoff + (r * PST + c) * 2, src + r * 64 + c);
    }
}
__device__ __forceinline__ float ldbf(const char* sm, int base, int idx) {
    return __bfloat162float(*(const __nv_bfloat16*)(sm + base + idx * 2));
}

__global__ __launch_bounds__(256, 1)
void attn_mma(const float* __restrict__ amask, const float* __restrict__ imask,
              const float* __restrict__ gate, float* __restrict__ outp)
{
    extern __shared__ char sm[];
    const uint32_t sb = smem_u32(sm);
    const int tid = threadIdx.x, warp = tid >> 5, lane = tid & 31;
    const int g = lane >> 2, t4 = lane & 3;
    const int bh = blockIdx.y, b = bh >> 4, h = bh & 15;
    const int l0 = blockIdx.x * 64;
    const int wm = warp * 16;
    const int wm2 = (warp >> 1) * 16, wn2 = (warp & 1) * 32;

    cp_tile64(sm, A_SQH, g_Qh + ((size_t)bh * SQ + l0) * DH, tid);
    cp_tile64(sm, A_SQL, g_Ql + ((size_t)bh * SQ + l0) * DH, tid);

    float cacc[4][4];
#pragma unroll
    for (int i = 0; i < 4; i++)
#pragma unroll
        for (int j = 0; j < 4; j++) cacc[i][j] = 0.f;
    float mrow[2] = {-1e30f, -1e30f}, ssum[2] = {0.f, 0.f};
    float* corr_sm = (float*)(sm + A_CORR);
    float* msk = (float*)(sm + A_MSK);

    // prefetch tile 0
    {
        cpa_tile64(sb, A_KV0 + KOH, g_Kh + ((size_t)bh * SQ) * DH, tid);
        cpa_tile64(sb, A_KV0 + KOL, g_Kl + ((size_t)bh * SQ) * DH, tid);
        cpa_tile64(sb, A_KV0 + VOH, g_Vh + ((size_t)bh * SQ) * DH, tid);
        cpa_tile64(sb, A_KV0 + VOL, g_Vl + ((size_t)bh * SQ) * DH, tid);
        const __nv_bfloat16* Eg = g_Eh + (size_t)(l0 + 960) * 64;
#pragma unroll
        for (int it = 0; it < 4; it++) {
            int i = tid + it * 256;
            int r = i >> 3, c = (i & 7) * 8;
            cpasync16(sb + A_E0 + (r * PST + c) * 2, Eg + r * 64 + c);
        }
        CP_COMMIT();
    }

    // ======================= main pass =======================
    for (int rt = 0; rt < 16; rt++) {
        const int pb = rt & 1;
        const int kvb = A_KV0 + pb * KVSET;
        const int eb = A_E0 + pb * ESET;
        const int r0 = rt * 64;

        if (rt + 1 < 16) {
            const int nb2 = A_KV0 + (pb ^ 1) * KVSET;
            const int r1 = r0 + 64;
            cpa_tile64(sb, nb2 + KOH, g_Kh + ((size_t)bh * SQ + r1) * DH, tid);
            cpa_tile64(sb, nb2 + KOL, g_Kl + ((size_t)bh * SQ + r1) * DH, tid);
            cpa_tile64(sb, nb2 + VOH, g_Vh + ((size_t)bh * SQ + r1) * DH, tid);
            cpa_tile64(sb, nb2 + VOL, g_Vl + ((size_t)bh * SQ + r1) * DH, tid);
            const __nv_bfloat16* Eg = g_Eh + (size_t)(l0 - r1 + 960) * 64;
            const int eb2 = A_E0 + (pb ^ 1) * ESET;
#pragma unroll
            for (int it = 0; it < 4; it++) {
                int i = tid + it * 256;
                int r = i >> 3, c = (i & 7) * 8;
                cpasync16(sb + eb2 + (r * PST + c) * 2, Eg + r * 64 + c);
            }
            CP_COMMIT();
            CP_WAIT(1);
        } else {
            CP_WAIT(0);
        }
        if (tid < 64) msk[tid] = amask[b * SQ + r0 + tid];
        __syncthreads();

        float sacc[8][4];
        if (warp < 4) {
#pragma unroll
            for (int j = 0; j < 8; j++)
#pragma unroll
                for (int p = 0; p < 4; p++) sacc[j][p] = 0.f;
#pragma unroll
            for (int k = 0; k < 4; k++) {
                const uint32_t ko = (k * 16 + (lane >> 4) * 8) * 2;
                uint32_t aH[4], aL[4];
                ldsm4(aH[0], aH[1], aH[2], aH[3],
                      sb + A_SQH + (wm + (lane & 15)) * PST * 2 + ko);
                ldsm4(aL[0], aL[1], aL[2], aL[3],
                      sb + A_SQL + (wm + (lane & 15)) * PST * 2 + ko);
#pragma unroll
                for (int nb = 0; nb < 4; nb++) {
                    uint32_t bH[4], bL[4];
                    ldsm4(bH[0], bH[1], bH[2], bH[3],
                          sb + kvb + KOH + (nb * 16 + (lane & 15)) * PST * 2 + ko);
                    ldsm4(bL[0], bL[1], bL[2], bL[3],
                          sb + kvb + KOL + (nb * 16 + (lane & 15)) * PST * 2 + ko);
                    mma16816(sacc[2 * nb], aH[0], aH[1], aH[2], aH[3], bH[0], bH[2]);
                    mma16816(sacc[2 * nb], aH[0], aH[1], aH[2], aH[3], bL[0], bL[2]);
                    mma16816(sacc[2 * nb], aL[0], aL[1], aL[2], aL[3], bH[0], bH[2]);
                    mma16816(sacc[2 * nb + 1], aH[0], aH[1], aH[2], aH[3], bH[1], bH[3]);
                    mma16816(sacc[2 * nb + 1], aH[0], aH[1], aH[2], aH[3], bL[1], bL[3]);
                    mma16816(sacc[2 * nb + 1], aL[0], aL[1], aL[2], aL[3], bH[1], bH[3]);
                }
            }
        } else {
            const int isP2 = (warp >= 6);
            const int m0p = (warp - (isP2 ? 6 : 4)) * 32;
            const int srcA = isP2 ? (kvb + KOH) : A_SQH;
            const int dstP = isP2 ? A_SP2 : A_SP1;
#pragma unroll
            for (int ch = 0; ch < 2; ch++) {
                float pacc[2][8][4];
#pragma unroll
                for (int s = 0; s < 2; s++)
#pragma unroll
                    for (int j = 0; j < 8; j++)
#pragma unroll
                        for (int p = 0; p < 4; p++) pacc[s][j][p] = 0.f;
#pragma unroll
                for (int k = 0; k < 4; k++) {
                    const uint32_t ko = (k * 16 + (lane >> 4) * 8) * 2;
                    uint32_t aU[4], aD[4];
                    ldsm4(aU[0], aU[1], aU[2], aU[3],
                          sb + srcA + (m0p + (lane & 15)) * PST * 2 + ko);
                    ldsm4(aD[0], aD[1], aD[2], aD[3],
                          sb + srcA + (m0p + 16 + (lane & 15)) * PST * 2 + ko);
#pragma unroll
                    for (int nb = 0; nb < 4; nb++) {
                        uint32_t be[4];
                        ldsm4(be[0], be[1], be[2], be[3],
                              sb + eb + (ch * 64 + nb * 16 + (lane & 15)) * PST * 2 + ko);
                        mma16816(pacc[0][2 * nb], aU[0], aU[1], aU[2], aU[3], be[0], be[2]);
                        mma16816(pacc[0][2 * nb + 1], aU[0], aU[1], aU[2], aU[3], be[1], be[3]);
                        mma16816(pacc[1][2 * nb], aD[0], aD[1], aD[2], aD[3], be[0], be[2]);
                        mma16816(pacc[1][2 * nb + 1], aD[0], aD[1], aD[2], aD[3], be[1], be[3]);
                    }
                }
#pragma unroll
                for (int s = 0; s < 2; s++)
#pragma unroll
                    for (int j = 0; j < 8; j++) {
                        int l = m0p + s * 16 + g;
                        int w = ch * 64 + 8 * j + 2 * t4;
                        *(uint32_t*)(sm + dstP + (l * P12 + w) * 2) =
                            pk2(pacc[s][j][0], pacc[s][j][1]);
                        *(uint32_t*)(sm + dstP + ((l + 8) * P12 + w) * 2) =
                            pk2(pacc[s][j][2], pacc[s][j][3]);
                    }
            }
        }
        __syncthreads();

        if (warp < 4) {
            const int l = wm + g;
#pragma unroll
            for (int j = 0; j < 8; j++) {
                const int r = 8 * j + 2 * t4;
                const int w = l - r + 63;
                sacc[j][0] = (sacc[j][0] + ldbf(sm, A_SP1, l * P12 + w)
                              + ldbf(sm, A_SP2, r * P12 + w)) * 0.125f + msk[r];
                sacc[j][1] = (sacc[j][1] + ldbf(sm, A_SP1, l * P12 + w - 1)
                              + ldbf(sm, A_SP2, (r + 1) * P12 + w - 1)) * 0.125f + msk[r + 1];
                sacc[j][2] = (sacc[j][2] + ldbf(sm, A_SP1, (l + 8) * P12 + w + 8)
                              + ldbf(sm, A_SP2, r * P12 + w + 8)) * 0.125f + msk[r];
                sacc[j][3] = (sacc[j][3] + ldbf(sm, A_SP1, (l + 8) * P12 + w + 7)
                              + ldbf(sm, A_SP2, (r + 1) * P12 + w + 7)) * 0.125f + msk[r + 1];
            }
            float mt0 = -1e30f, mt1 = -1e30f;
#pragma unroll
            for (int j = 0; j < 8; j++) {
                mt0 = fmaxf(mt0, fmaxf(sacc[j][0], sacc[j][1]));
                mt1 = fmaxf(mt1, fmaxf(sacc[j][2], sacc[j][3]));
            }
            mt0 = fmaxf(mt0, __shfl_xor_sync(0xffffffffu, mt0, 1));
            mt0 = fmaxf(mt0, __shfl_xor_sync(0xffffffffu, mt0, 2));
            mt1 = fmaxf(mt1, __shfl_xor_sync(0xffffffffu, mt1, 1));
            mt1 = fmaxf(mt1, __shfl_xor_sync(0xffffffffu, mt1, 2));
            float mn0 = fmaxf(mrow[0], mt0), mn1 = fmaxf(mrow[1], mt1);
            float cr0 = __expf(mrow[0] - mn0), cr1 = __expf(mrow[1] - mn1);
            mrow[0] = mn0; mrow[1] = mn1;
            float ps0 = 0.f, ps1 = 0.f;
#pragma unroll
            for (int j = 0; j < 8; j++) {
                float p00 = __expf(sacc[j][0] - mn0), p01 = __expf(sacc[j][1] - mn0);
                float p10 = __expf(sacc[j][2] - mn1), p11 = __expf(sacc[j][3] - mn1);
                ps0 += p00 + p01; ps1 += p10 + p11;
                int cidx = 8 * j + 2 * t4;
                uint32_t h0 = pk2(p00, p01), h1 = pk2(p10, p11);
                *(uint32_t*)(sm + A_SPH + (l * PST + cidx) * 2) = h0;
                *(uint32_t*)(sm + A_SPH + ((l + 8) * PST + cidx) * 2) = h1;
                __nv_bfloat162 hh0 = *(__nv_bfloat162*)&h0;
                __nv_bfloat162 hh1 = *(__nv_bfloat162*)&h1;
                *(uint32_t*)(sm + A_SPL + (l * PST + cidx) * 2) =
                    pk2(p00 - __bfloat162float(hh0.x), p01 - __bfloat162float(hh0.y));
                *(uint32_t*)(sm + A_SPL + ((l + 8) * PST + cidx) * 2) =
                    pk2(p10 - __bfloat162float(hh1.x), p11 - __bfloat162float(hh1.y));
            }
            ps0 += __shfl_xor_sync(0xffffffffu, ps0, 1);
            ps0 += __shfl_xor_sync(0xffffffffu, ps0, 2);
            ps1 += __shfl_xor_sync(0xffffffffu, ps1, 1);
            ps1 += __shfl_xor_sync(0xffffffffu, ps1, 2);
            ssum[0] = ssum[0] * cr0 + ps0;
            ssum[1] = ssum[1] * cr1 + ps1;
            if (t4 == 0) { corr_sm[l] = cr0; corr_sm[l + 8] = cr1; }
        }
        __syncthreads();

        {
            float c0r = corr_sm[wm2 + g], c1r = corr_sm[wm2 + 8 + g];
#pragma unroll
            for (int nf = 0; nf < 4; nf++) {
                cacc[nf][0] *= c0r; cacc[nf][1] *= c0r;
                cacc[nf][2] *= c1r; cacc[nf][3] *= c1r;
            }
#pragma unroll
            for (int kk = 0; kk < 4; kk++) {
                const uint32_t ko = (kk * 16 + (lane >> 4) * 8) * 2;
                uint32_t aPh[4], aPl[4];
                ldsm4(aPh[0], aPh[1], aPh[2], aPh[3],
                      sb + A_SPH + (wm2 + (lane & 15)) * PST * 2 + ko);
                ldsm4(aPl[0], aPl[1], aPl[2], aPl[3],
                      sb + A_SPL + (wm2 + (lane & 15)) * PST * 2 + ko);
#pragma unroll
                for (int dh = 0; dh < 2; dh++) {
                    const uint32_t trow = (kk * 16 + (lane & 7) + 8 * ((lane >> 3) & 1)) * PST;
                    const uint32_t tcol = wn2 + dh * 16 + ((lane >> 4) & 1) * 8;
                    uint32_t bh2[4], bl2[4];
                    ldsm4t(bh2[0], bh2[1], bh2[2], bh2[3],
                           sb + kvb + VOH + (trow + tcol) * 2);
                    ldsm4t(bl2[0], bl2[1], bl2[2], bl2[3],
                           sb + kvb + VOL + (trow + tcol) * 2);
                    const int nf = dh * 2;
                    mma16816(cacc[nf], aPh[0], aPh[1], aPh[2], aPh[3], bh2[0], bh2[1]);
                    mma16816(cacc[nf], aPh[0], aPh[1], aPh[2], aPh[3], bl2[0], bl2[1]);
                    mma16816(cacc[nf], aPl[0], aPl[1], aPl[2], aPl[3], bh2[0], bh2[1]);
                    mma16816(cacc[nf + 1], aPh[0], aPh[1], aPh[2], aPh[3], bh2[2], bh2[3]);
                    mma16816(cacc[nf + 1], aPh[0], aPh[1], aPh[2], aPh[3], bl2[2], bl2[3]);
                    mma16816(cacc[nf + 1], aPl[0], aPl[1], aPl[2], aPl[3], bh2[2], bh2[3]);
                }
            }
        }
        __syncthreads();
    }

    // stash main ctx + ssum, reset
    {
        float* stash = (float*)(sm + A_SP1);
#pragma unroll
        for (int nf = 0; nf < 4; nf++) {
            int d = wn2 + 8 * nf + 2 * t4;
            stash[(wm2 + g) * 68 + d] = cacc[nf][0];
            stash[(wm2 + g) * 68 + d + 1] = cacc[nf][1];
            stash[(wm2 + 8 + g) * 68 + d] = cacc[nf][2];
            stash[(wm2 + 8 + g) * 68 + d + 1] = cacc[nf][3];
            cacc[nf][0] = cacc[nf][1] = cacc[nf][2] = cacc[nf][3] = 0.f;
        }
        if (warp < 4 && t4 == 0) {
            ((float*)(sm + A_SSM))[wm + g] = ssum[0];
            ((float*)(sm + A_SSM))[wm + g + 8] = ssum[1];
        }
        mrow[0] = mrow[1] = -1e30f; ssum[0] = ssum[1] = 0.f;
    }

    // ======================= instruct pass =======================
    for (int rt = 0; rt < 2; rt++) {
        const int r0 = rt * 64;
        const int kvb = A_KV0;
        __syncthreads();
        cp_tile64(sm, kvb + KOH, g_IKh + ((size_t)bh * LI + r0) * DH, tid);
        cp_tile64(sm, kvb + KOL, g_IKl + ((size_t)bh * LI + r0) * DH, tid);
        cp_tile64(sm, kvb + VOH, g_IVh + ((size_t)bh * LI + r0) * DH, tid);
        cp_tile64(sm, kvb + VOL, g_IVl + ((size_t)bh * LI + r0) * DH, tid);
        if (tid < 64) msk[tid] = imask[b * LI + r0 + tid];
        __syncthreads();

        if (warp < 4) {
            float sacc[8][4];
#pragma unroll
            for (int j = 0; j < 8; j++)
#pragma unroll
                for (int p = 0; p < 4; p++) sacc[j][p] = 0.f;
#pragma unroll
            for (int k = 0; k < 4; k++) {
                const uint32_t ko = (k * 16 + (lane >> 4) * 8) * 2;
                uint32_t aH[4], aL[4];
                ldsm4(aH[0], aH[1], aH[2], aH[3],
                      sb + A_SQH + (wm + (lane & 15)) * PST * 2 + ko);
                ldsm4(aL[0], aL[1], aL[2], aL[3],
                      sb + A_SQL + (wm + (lane & 15)) * PST * 2 + ko);
#pragma unroll
                for (int nb = 0; nb < 4; nb++) {
                    uint32_t bH[4], bL[4];
                    ldsm4(bH[0], bH[1], bH[2], bH[3],
                          sb + kvb + KOH + (nb * 16 + (lane & 15)) * PST * 2 + ko);
                    ldsm4(bL[0], bL[1], bL[2], bL[3],
                          sb + kvb + KOL + (nb * 16 + (lane & 15)) * PST * 2 + ko);
                    mma16816(sacc[2 * nb], aH[0], aH[1], aH[2], aH[3], bH[0], bH[2]);
                    mma16816(sacc[2 * nb], aH[0], aH[1], aH[2], aH[3], bL[0], bL[2]);
                    mma16816(sacc[2 * nb], aL[0], aL[1], aL[2], aL[3], bH[0], bH[2]);
                    mma16816(sacc[2 * nb + 1], aH[0], aH[1], aH[2], aH[3], bH[1], bH[3]);
                    mma16816(sacc[2 * nb + 1], aH[0], aH[1], aH[2], aH[3], bL[1], bL[3]);
                    mma16816(sacc[2 * nb + 1], aL[0], aL[1], aL[2], aL[3], bH[1], bH[3]);
                }
            }
            const int l = wm + g;
            float mt0 = -1e30f, mt1 = -1e30f;
#pragma unroll
            for (int j = 0; j < 8; j++) {
                const int r = 8 * j + 2 * t4;
                sacc[j][0] = sacc[j][0] * 0.125f + msk[r];
                sacc[j][1] = sacc[j][1] * 0.125f + msk[r + 1];
                sacc[j][2] = sacc[j][2] * 0.125f + msk[r];
                sacc[j][3] = sacc[j][3] * 0.125f + msk[r + 1];
                mt0 = fmaxf(mt0, fmaxf(sacc[j][0], sacc[j][1]));
                mt1 = fmaxf(mt1, fmaxf(sacc[j][2], sacc[j][3]));
            }
            mt0 = fmaxf(mt0, __shfl_xor_sync(0xffffffffu, mt0, 1));
            mt0 = fmaxf(mt0, __shfl_xor_sync(0xffffffffu, mt0, 2));
            mt1 = fmaxf(mt1, __shfl_xor_sync(0xffffffffu, mt1, 1));
            mt1 = fmaxf(mt1, __shfl_xor_sync(0xffffffffu, mt1, 2));
            float mn0 = fmaxf(mrow[0], mt0), mn1 = fmaxf(mrow[1], mt1);
            float cr0 = __expf(mrow[0] - mn0), cr1 = __expf(mrow[1] - mn1);
            mrow[0] = mn0; mrow[1] = mn1;
            float ps0 = 0.f, ps1 = 0.f;
#pragma unroll
            for (int j = 0; j < 8; j++) {
                float p00 = __expf(sacc[j][0] - mn0), p01 = __expf(sacc[j][1] - mn0);
                float p10 = __expf(sacc[j][2] - mn1), p11 = __expf(sacc[j][3] - mn1);
                ps0 += p00 + p01; ps1 += p10 + p11;
                int cidx = 8 * j + 2 * t4;
                uint32_t h0 = pk2(p00, p01), h1 = pk2(p10, p11);
                *(uint32_t*)(sm + A_SPH + (l * PST + cidx) * 2) = h0;
                *(uint32_t*)(sm + A_SPH + ((l + 8) * PST + cidx) * 2) = h1;
                __nv_bfloat162 hh0 = *(__nv_bfloat162*)&h0;
                __nv_bfloat162 hh1 = *(__nv_bfloat162*)&h1;
                *(uint32_t*)(sm + A_SPL + (l * PST + cidx) * 2) =
                    pk2(p00 - __bfloat162float(hh0.x), p01 - __bfloat162float(hh0.y));
                *(uint32_t*)(sm + A_SPL + ((l + 8) * PST + cidx) * 2) =
                    pk2(p10 - __bfloat162float(hh1.x), p11 - __bfloat162float(hh1.y));
            }
            ps0 += __shfl_xor_sync(0xffffffffu, ps0, 1);
            ps0 += __shfl_xor_sync(0xffffffffu, ps0, 2);
            ps1 += __shfl_xor_sync(0xffffffffu, ps1, 1);
            ps1 += __shfl_xor_sync(0xffffffffu, ps1, 2);
            ssum[0] = ssum[0] * cr0 + ps0;
            ssum[1] = ssum[1] * cr1 + ps1;
            if (t4 == 0) { corr_sm[l] = cr0; corr_sm[l + 8] = cr1; }
        }
        __syncthreads();

        {
            float c0r = corr_sm[wm2 + g], c1r = corr_sm[wm2 + 8 + g];
#pragma unroll
            for (int nf = 0; nf < 4; nf++) {
                cacc[nf][0] *= c0r; cacc[nf][1] *= c0r;
                cacc[nf][2] *= c1r; cacc[nf][3] *= c1r;
            }
#pragma unroll
            for (int kk = 0; kk < 4; kk++) {
                const uint32_t ko = (kk * 16 + (lane >> 4) * 8) * 2;
                uint32_t aPh[4], aPl[4];
                ldsm4(aPh[0], aPh[1], aPh[2], aPh[3],
                      sb + A_SPH + (wm2 + (lane & 15)) * PST * 2 + ko);
                ldsm4(aPl[0], aPl[1], aPl[2], aPl[3],
                      sb + A_SPL + (wm2 + (lane & 15)) * PST * 2 + ko);
#pragma unroll
                for (int dh = 0; dh < 2; dh++) {
                    const uint32_t trow = (kk * 16 + (lane & 7) + 8 * ((lane >> 3) & 1)) * PST;
                    const uint32_t tcol = wn2 + dh * 16 + ((lane >> 4) & 1) * 8;
                    uint32_t bh2[4], bl2[4];
                    ldsm4t(bh2[0], bh2[1], bh2[2], bh2[3],
                           sb + kvb + VOH + (trow + tcol) * 2);
                    ldsm4t(bl2[0], bl2[1], bl2[2], bl2[3],
                           sb + kvb + VOL + (trow + tcol) * 2);
                    const int nf = dh * 2;
                    mma16816(cacc[nf], aPh[0], aPh[1], aPh[2], aPh[3], bh2[0], bh2[1]);
                    mma16816(cacc[nf], aPh[0], aPh[1], aPh[2], aPh[3], bl2[0], bl2[1]);
                    mma16816(cacc[nf], aPl[0], aPl[1], aPl[2], aPl[3], bh2[0], bh2[1]);
                    mma16816(cacc[nf + 1], aPh[0], aPh[1], aPh[2], aPh[3], bh2[2], bh2[3]);
                    mma16816(cacc[nf + 1], aPh[0], aPh[1], aPh[2], aPh[3], bl2[2], bl2[3]);
                    mma16816(cacc[nf + 1], aPl[0], aPl[1], aPl[2], aPl[3], bh2[2], bh2[3]);
                }
            }
        }
    }

    __syncthreads();
    if (warp < 4 && t4 == 0) {
        ((float*)(sm + A_SSI))[wm + g] = ssum[0];
        ((float*)(sm + A_SSI))[wm + g + 8] = ssum[1];
    }
    __syncthreads();

    {
        const float tg = tanhf(gate[h]);
        const float* stash = (const float*)(sm + A_SP1);
        const float* ssm = (const float*)(sm + A_SSM);
        const float* ssi = (const float*)(sm + A_SSI);
        const float rnm0 = 1.f / ssm[wm2 + g], rni0 = tg / ssi[wm2 + g];
        const float rnm1 = 1.f / ssm[wm2 + 8 + g], rni1 = tg / ssi[wm2 + 8 + g];
#pragma unroll
        for (int nf = 0; nf < 4; nf++) {
            const int d = wn2 + 8 * nf + 2 * t4;
            float2 o0, o1;
            o0.x = stash[(wm2 + g) * 68 + d] * rnm0 + cacc[nf][0] * rni0;
            o0.y = stash[(wm2 + g) * 68 + d + 1] * rnm0 + cacc[nf][1] * rni0;
            o1.x = stash[(wm2 + 8 + g) * 68 + d] * rnm1 + cacc[nf][2] * rni1;
            o1.y = stash[(wm2 + 8 + g) * 68 + d + 1] * rnm1 + cacc[nf][3] * rni1;
            *(float2*)(outp + ((size_t)(b * SQ + l0 + wm2 + g)) * HIDDEN + h * DH + d) = o0;
            *(float2*)(outp + ((size_t)(b * SQ + l0 + wm2 + 8 + g)) * HIDDEN + h * DH + d) = o1;
        }
    }
}

// ---------------------------------------------------------------------------
extern "C" void kernel_launch(void* const* d_in, const int* in_sizes, int n_in,
                              void* d_out, int out_size)
{
    (void)in_sizes; (void)n_in; (void)out_size;
    const float* hs    = (const float*)d_in[0];
    const float* amask = (const float*)d_in[1];
    const float* ihs   = (const float*)d_in[2];
    const float* imask = (const float*)d_in[3];
    const float* Wq    = (const float*)d_in[4];
    const float* bq    = (const float*)d_in[5];
    const float* Wk    = (const float*)d_in[6];
    const float* bk    = (const float*)d_in[7];
    const float* Wv    = (const float*)d_in[8];
    const float* bv    = (const float*)d_in[9];
    const float* gate  = (const float*)d_in[10];
    const float* dist  = (const float*)d_in[11];
    float* out = (float*)d_out;

    __nv_bfloat16 *qh, *ql, *kh, *kl, *vh, *vl, *ikh, *ikl, *ivh, *ivl, *eh;
    __nv_bfloat16 *xc, *ixc, *wc;
    cudaGetSymbolAddress((void**)&qh, g_Qh);
    cudaGetSymbolAddress((void**)&ql, g_Ql);
    cudaGetSymbolAddress((void**)&kh, g_Kh);
    cudaGetSymbolAddress((void**)&kl, g_Kl);
    cudaGetSymbolAddress((void**)&vh, g_Vh);
    cudaGetSymbolAddress((void**)&vl, g_Vl);
    cudaGetSymbolAddress((void**)&ikh, g_IKh);
    cudaGetSymbolAddress((void**)&ikl, g_IKl);
    cudaGetSymbolAddress((void**)&ivh, g_IVh);
    cudaGetSymbolAddress((void**)&ivl, g_IVl);
    cudaGetSymbolAddress((void**)&eh, g_Eh);
    cudaGetSymbolAddress((void**)&xc, g_Xcat);
    cudaGetSymbolAddress((void**)&ixc, g_IXcat);
    cudaGetSymbolAddress((void**)&wc, g_Wcat);

    cudaFuncSetAttribute(gemm_mma, cudaFuncAttributeMaxDynamicSharedMemorySize, GEMM_SMEM);
    cudaFuncSetAttribute(attn_mma, cudaFuncAttributeMaxDynamicSharedMemorySize, A_TOTAL);

    conv_x<<<(NB * SQ * HIDDEN / 4 + 255) / 256, 256>>>((const float4*)hs, xc,
                                                        NB * SQ * HIDDEN / 4);
    conv_x<<<(NB * LI * HIDDEN / 4 + 255) / 256, 256>>>((const float4*)ihs, ixc,
                                                        NB * LI * HIDDEN / 4);
    conv_w<<<dim3(32, 32, 3), 256>>>(Wq, Wk, Wv, wc);
    conv_e<<<(2048 * 64 + 255) / 256, 256>>>(dist, eh);

    gemm_mma<<<dim3(24, 32), 256, GEMM_SMEM>>>(xc, 10, SQ, wc, bq, bk, bv,
                                               qh, ql, kh, kl, vh, vl, 0);
    gemm_mma<<<dim3(16, 4), 256, GEMM_SMEM>>>(ixc, 7, LI, wc, bq, bk, bv,
                                              qh, ql, ikh, ikl, ivh, ivl, 1024);

    attn_mma<<<dim3(SQ / 64, BHN), 256, A_TOTAL>>>(amask, imask, gate, out);
}

// round 7
// speedup vs baseline: 4.7896x; 1.1129x over previous
#include <cuda_runtime.h>
#include <cuda_bf16.h>
#include <math.h>
#include <cstdint>

#define NB 4
#define NH 16
#define DH 64
#define SQ 1024
#define LI 128
#define HIDDEN 1024
#define BHN (NB * NH)
#define KW 2048   // stored operand width (hi|lo)

// ---------------- scratch ---------------------------------------------------
__device__ __align__(16) __nv_bfloat16 g_Qh[BHN * SQ * DH];
__device__ __align__(16) __nv_bfloat16 g_Ql[BHN * SQ * DH];
__device__ __align__(16) __nv_bfloat16 g_Kh[BHN * SQ * DH];
__device__ __align__(16) __nv_bfloat16 g_Kl[BHN * SQ * DH];
__device__ __align__(16) __nv_bfloat16 g_Vh[BHN * SQ * DH];
__device__ __align__(16) __nv_bfloat16 g_Vl[BHN * SQ * DH];
__device__ __align__(16) __nv_bfloat16 g_IKh[BHN * LI * DH];
__device__ __align__(16) __nv_bfloat16 g_IKl[BHN * LI * DH];
__device__ __align__(16) __nv_bfloat16 g_IVh[BHN * LI * DH];
__device__ __align__(16) __nv_bfloat16 g_IVl[BHN * LI * DH];
__device__ __align__(16) __nv_bfloat16 g_Eh[2048 * DH];

__device__ __align__(16) __nv_bfloat16 g_Xcat[NB * SQ * KW];
__device__ __align__(16) __nv_bfloat16 g_IXcat[NB * LI * KW];
__device__ __align__(16) __nv_bfloat16 g_Wcat[3 * HIDDEN * KW];

// ---------------- helpers ---------------------------------------------------
__device__ __forceinline__ uint32_t smem_u32(const void* p) {
    uint32_t a;
    asm("{ .reg .u64 t; cvta.to.shared.u64 t, %1; cvt.u32.u64 %0, t; }" : "=r"(a) : "l"(p));
    return a;
}
__device__ __forceinline__ void ldsm4(uint32_t& r0, uint32_t& r1, uint32_t& r2,
                                      uint32_t& r3, uint32_t addr) {
    asm volatile("ldmatrix.sync.aligned.m8n8.x4.shared.b16 {%0,%1,%2,%3}, [%4];"
                 : "=r"(r0), "=r"(r1), "=r"(r2), "=r"(r3) : "r"(addr));
}
__device__ __forceinline__ void ldsm4t(uint32_t& r0, uint32_t& r1, uint32_t& r2,
                                       uint32_t& r3, uint32_t addr) {
    asm volatile("ldmatrix.sync.aligned.m8n8.x4.trans.shared.b16 {%0,%1,%2,%3}, [%4];"
                 : "=r"(r0), "=r"(r1), "=r"(r2), "=r"(r3) : "r"(addr));
}
__device__ __forceinline__ void mma16816(float* c, uint32_t a0, uint32_t a1,
                                         uint32_t a2, uint32_t a3,
                                         uint32_t b0, uint32_t b1) {
    asm volatile(
        "mma.sync.aligned.m16n8k16.row.col.f32.bf16.bf16.f32 "
        "{%0,%1,%2,%3}, {%4,%5,%6,%7}, {%8,%9}, {%0,%1,%2,%3};"
        : "+f"(c[0]), "+f"(c[1]), "+f"(c[2]), "+f"(c[3])
        : "r"(a0), "r"(a1), "r"(a2), "r"(a3), "r"(b0), "r"(b1));
}
__device__ __forceinline__ uint32_t pk2(float a, float b) {
    __nv_bfloat162 t = __floats2bfloat162_rn(a, b);
    return *(uint32_t*)&t;
}
__device__ __forceinline__ void cpasync16(uint32_t dst, const void* src) {
    asm volatile("cp.async.cg.shared.global [%0], [%1], 16;" :: "r"(dst), "l"(src));
}
#define CP_COMMIT() asm volatile("cp.async.commit_group;" ::: "memory")
#define CP_WAIT(n)  asm volatile("cp.async.wait_group %0;" :: "n"(n) : "memory")

// ---------------------------------------------------------------------------
// Conversions (merged X-main / X-instruct / E in one launch)
// ---------------------------------------------------------------------------
#define NX_MAIN (NB * SQ * HIDDEN / 4 / 256)     // 4096 blocks
#define NX_INST (NB * LI * HIDDEN / 4 / 256)     // 512 blocks
#define NX_E    (2048 * 64 / 256)                // 512 blocks

__global__ __launch_bounds__(256)
void conv_all(const float4* __restrict__ xm, __nv_bfloat16* __restrict__ dm,
              const float4* __restrict__ xi, __nv_bfloat16* __restrict__ di,
              const float* __restrict__ dist, __nv_bfloat16* __restrict__ eh)
{
    int blk = blockIdx.x;
    if (blk >= NX_MAIN + NX_INST) {
        int i = (blk - NX_MAIN - NX_INST) * 256 + threadIdx.x;
        float v = (i < 2047 * 64) ? dist[i] : 0.f;
        eh[i] = __float2bfloat16(v);
        return;
    }
    const float4* src = (blk < NX_MAIN) ? xm : xi;
    __nv_bfloat16* dst = (blk < NX_MAIN) ? dm : di;
    int i = ((blk < NX_MAIN) ? blk : blk - NX_MAIN) * 256 + threadIdx.x;
    int row = i >> 8, c4 = (i & 255) * 4;
    float4 v = src[i];
    __nv_bfloat16 hx = __float2bfloat16(v.x), hy = __float2bfloat16(v.y);
    __nv_bfloat16 hz = __float2bfloat16(v.z), hw = __float2bfloat16(v.w);
    __nv_bfloat16 lx = __float2bfloat16(v.x - __bfloat162float(hx));
    __nv_bfloat16 ly = __float2bfloat16(v.y - __bfloat162float(hy));
    __nv_bfloat16 lz = __float2bfloat16(v.z - __bfloat162float(hz));
    __nv_bfloat16 lw = __float2bfloat16(v.w - __bfloat162float(hw));
    uint2 H, L;
    H.x = (uint32_t)__bfloat16_as_ushort(hx) | ((uint32_t)__bfloat16_as_ushort(hy) << 16);
    H.y = (uint32_t)__bfloat16_as_ushort(hz) | ((uint32_t)__bfloat16_as_ushort(hw) << 16);
    L.x = (uint32_t)__bfloat16_as_ushort(lx) | ((uint32_t)__bfloat16_as_ushort(ly) << 16);
    L.y = (uint32_t)__bfloat16_as_ushort(lz) | ((uint32_t)__bfloat16_as_ushort(lw) << 16);
    __nv_bfloat16* rb = dst + (size_t)row * KW + c4;
    *(uint2*)(rb)        = H;
    *(uint2*)(rb + 1024) = L;
}

__global__ __launch_bounds__(256)
void conv_w(const float* __restrict__ Wq, const float* __restrict__ Wk,
            const float* __restrict__ Wv, __nv_bfloat16* __restrict__ dst)
{
    const float* W = (blockIdx.z == 0) ? Wq : (blockIdx.z == 1) ? Wk : Wv;
    __shared__ float t[32][33];
    int tx = threadIdx.x & 31, ty = threadIdx.x >> 5;
    int n = blockIdx.x * 32 + tx, k0 = blockIdx.y * 32;
#pragma unroll
    for (int j = 0; j < 4; j++)
        t[ty + 8 * j][tx] = W[(size_t)(k0 + ty + 8 * j) * HIDDEN + n];
    __syncthreads();
    size_t nrow = (size_t)blockIdx.z * HIDDEN + blockIdx.x * 32;
#pragma unroll
    for (int j = 0; j < 4; j++) {
        float v = t[tx][ty + 8 * j];
        __nv_bfloat16 h = __float2bfloat16(v);
        __nv_bfloat16 l = __float2bfloat16(v - __bfloat162float(h));
        __nv_bfloat16* o = dst + (nrow + ty + 8 * j) * KW + k0 + tx;
        o[0]    = h;
        o[1024] = l;
    }
}

// ---------------------------------------------------------------------------
// Merged projection GEMM: CTA tile 128x256, warp tile 64x64 (8 warps 2x4).
// K'=3072 virtual (3-term split) over 2048-wide stores. One launch covers
// main (blocks 0..383) and instruct (blocks 384..415).
// ---------------------------------------------------------------------------
#define KC 64
#define AST 72
#define TA (128 * AST * 2)     // 18432
#define TB (256 * AST * 2)     // 36864
#define GEMM_SMEM (2 * (TA + TB))   // 110592

__global__ __launch_bounds__(256, 1)
void gemm_mma(const __nv_bfloat16* __restrict__ Am,
              const __nv_bfloat16* __restrict__ Ai,
              const __nv_bfloat16* __restrict__ Bm,
              const float* __restrict__ bq, const float* __restrict__ bk,
              const float* __restrict__ bv,
              __nv_bfloat16* oQh, __nv_bfloat16* oQl,
              __nv_bfloat16* oKh, __nv_bfloat16* oKl,
              __nv_bfloat16* oVh, __nv_bfloat16* oVl,
              __nv_bfloat16* oIKh, __nv_bfloat16* oIKl,
              __nv_bfloat16* oIVh, __nv_bfloat16* oIVl)
{
    extern __shared__ char smem[];
    const uint32_t sb = smem_u32(smem);
    const int tid = threadIdx.x, warp = tid >> 5, lane = tid & 31;

    const __nv_bfloat16* A;
    int msh, Slen, m0, n0g, inst;
    {
        int blk = blockIdx.x;
        if (blk < 384) {
            A = Am; msh = 10; Slen = SQ; inst = 0;
            m0 = (blk / 12) * 128; n0g = (blk % 12) * 256;
        } else {
            blk -= 384;
            A = Ai; msh = 7; Slen = LI; inst = 1;
            m0 = (blk / 8) * 128; n0g = 1024 + (blk % 8) * 256;
        }
    }
    const int wm = (warp >> 2) * 64, wn = (warp & 3) * 64;

    const int cr = tid >> 3, cko = (tid & 7) * 8;
    const __nv_bfloat16* Ag = A + (size_t)(m0 + cr) * KW + cko;
    const __nv_bfloat16* Bg = Bm + (size_t)(n0g + cr) * KW + cko;
    const uint32_t sAo = (cr * AST + cko) * 2;

    float acc[4][8][4];
#pragma unroll
    for (int i = 0; i < 4; i++)
#pragma unroll
        for (int j = 0; j < 8; j++)
#pragma unroll
            for (int p = 0; p < 4; p++) acc[i][j][p] = 0.f;

#pragma unroll
    for (int i = 0; i < 4; i++)
        cpasync16(sb + sAo + i * 32 * AST * 2, Ag + (size_t)(i * 32) * KW);
#pragma unroll
    for (int i = 0; i < 8; i++)
        cpasync16(sb + TA + sAo + i * 32 * AST * 2, Bg + (size_t)(i * 32) * KW);
    CP_COMMIT();

    const int NCH = 48;
    for (int c = 0; c < NCH; c++) {
        const int p = c & 1;
        if (c + 1 < NCH) {
            const int pn = (c + 1) & 1;
            const int cn = c + 1;
            const int aoff = (cn < 16) ? cn * 64 : cn * 64 - 1024;
            const int boff = (cn < 32) ? cn * 64 : cn * 64 - 2048;
#pragma unroll
            for (int i = 0; i < 4; i++)
                cpasync16(sb + pn * (TA + TB) + sAo + i * 32 * AST * 2,
                          Ag + (size_t)(i * 32) * KW + aoff);
#pragma unroll
            for (int i = 0; i < 8; i++)
                cpasync16(sb + pn * (TA + TB) + TA + sAo + i * 32 * AST * 2,
                          Bg + (size_t)(i * 32) * KW + boff);
            CP_COMMIT();
            CP_WAIT(1);
        } else {
            CP_WAIT(0);
        }
        __syncthreads();

        const uint32_t aw = sb + p * (TA + TB) +
                            ((wm + (lane & 15)) * AST + (lane >> 4) * 8) * 2;
        const uint32_t bw = sb + p * (TA + TB) + TA +
                            ((wn + (lane & 15)) * AST + (lane >> 4) * 8) * 2;
#pragma unroll
        for (int k16 = 0; k16 < 4; k16++) {
            const uint32_t ko = k16 * 32;
            uint32_t a[4][4], b[4][4];
#pragma unroll
            for (int mt = 0; mt < 4; mt++)
                ldsm4(a[mt][0], a[mt][1], a[mt][2], a[mt][3],
                      aw + mt * 16 * AST * 2 + ko);
#pragma unroll
            for (int nb = 0; nb < 4; nb++)
                ldsm4(b[nb][0], b[nb][1], b[nb][2], b[nb][3],
                      bw + nb * 16 * AST * 2 + ko);
#pragma unroll
            for (int mt = 0; mt < 4; mt++)
#pragma unroll
                for (int nb = 0; nb < 4; nb++) {
                    mma16816(acc[mt][2 * nb], a[mt][0], a[mt][1], a[mt][2], a[mt][3],
                             b[nb][0], b[nb][2]);
                    mma16816(acc[mt][2 * nb + 1], a[mt][0], a[mt][1], a[mt][2], a[mt][3],
                             b[nb][1], b[nb][3]);
                }
        }
        __syncthreads();
    }

#pragma unroll
    for (int nt = 0; nt < 8; nt++) {
        const int n = n0g + wn + nt * 8 + (lane & 3) * 2;
        const int wsel = n >> 10, nn = n & 1023;
        const float* bias = (wsel == 0) ? bq : (wsel == 1) ? bk : bv;
        __nv_bfloat16* ph;
        __nv_bfloat16* pl;
        if (inst) {
            ph = (wsel == 1) ? oIKh : oIVh;
            pl = (wsel == 1) ? oIKl : oIVl;
        } else {
            ph = (wsel == 0) ? oQh : (wsel == 1) ? oKh : oVh;
            pl = (wsel == 0) ? oQl : (wsel == 1) ? oKl : oVl;
        }
        const float b0 = bias[nn], b1 = bias[nn + 1];
        const size_t hoff = ((size_t)(nn >> 6)) * Slen;
        const int d = nn & 63;
#pragma unroll
        for (int mt = 0; mt < 4; mt++) {
#pragma unroll
            for (int half = 0; half < 2; half++) {
                const int r = m0 + wm + mt * 16 + (lane >> 2) + half * 8;
                const int bb = r >> msh, t = r - (bb << msh);
                float vx = acc[mt][nt][half * 2 + 0] + b0;
                float vy = acc[mt][nt][half * 2 + 1] + b1;
                __nv_bfloat16 hx = __float2bfloat16(vx);
                __nv_bfloat16 hy = __float2bfloat16(vy);
                float lxf = vx - __bfloat162float(hx);
                float lyf = vy - __bfloat162float(hy);
                size_t off = ((size_t)bb * NH * Slen + hoff + t) * DH + d;
                *(uint32_t*)(ph + off) =
                    (uint32_t)__bfloat16_as_ushort(hx) |
                    ((uint32_t)__bfloat16_as_ushort(hy) << 16);
                *(uint32_t*)(pl + off) = pk2(lxf, lyf);
            }
        }
    }
}

// ---------------------------------------------------------------------------
// Tensor-core attention (double-buffered cp.async; masks preloaded to smem).
// ---------------------------------------------------------------------------
#define PST 72
#define P12 136
#define A_SQH 0
#define A_SQL 9216
#define A_KV0 18432
#define KVSET 36864
#define KOH 0
#define KOL 9216
#define VOH 18432
#define VOL 27648
#define A_E0 92160
#define ESET 18432
#define A_SPH 129024
#define A_SPL 138240
#define A_SP1 147456
#define A_SP2 164864
#define A_CORR 182272
#define A_SSM 182528
#define A_SSI 182784
#define A_AMSK 183040
#define A_IMSK 187136
#define A_TOTAL 187648

__device__ __forceinline__ void cp_tile64(char* sm, int dstoff,
                                          const __nv_bfloat16* src, int tid)
{
#pragma unroll
    for (int it = 0; it < 2; it++) {
        int i = tid + it * 256;
        int r = i >> 3, c = (i & 7) * 8;
        *(uint4*)(sm + dstoff + (r * PST + c) * 2) = *(const uint4*)(src + r * 64 + c);
    }
}
__device__ __forceinline__ void cpa_tile64(uint32_t sb, int dstoff,
                                           const __nv_bfloat16* src, int tid)
{
#pragma unroll
    for (int it = 0; it < 2; it++) {
        int i = tid + it * 256;
        int r = i >> 3, c = (i & 7) * 8;
        cpasync16(sb + dstoff + (r * PST + c) * 2, src + r * 64 + c);
    }
}
__device__ __forceinline__ float ldbf(const char* sm, int base, int idx) {
    return __bfloat162float(*(const __nv_bfloat16*)(sm + base + idx * 2));
}

__global__ __launch_bounds__(256, 1)
void attn_mma(const float* __restrict__ amask, const float* __restrict__ imask,
              const float* __restrict__ gate, float* __restrict__ outp)
{
    extern __shared__ char sm[];
    const uint32_t sb = smem_u32(sm);
    const int tid = threadIdx.x, warp = tid >> 5, lane = tid & 31;
    const int g = lane >> 2, t4 = lane & 3;
    const int bh = blockIdx.y, b = bh >> 4, h = bh & 15;
    const int l0 = blockIdx.x * 64;
    const int wm = warp * 16;
    const int wm2 = (warp >> 1) * 16, wn2 = (warp & 1) * 32;

    cp_tile64(sm, A_SQH, g_Qh + ((size_t)bh * SQ + l0) * DH, tid);
    cp_tile64(sm, A_SQL, g_Ql + ((size_t)bh * SQ + l0) * DH, tid);
    ((float4*)(sm + A_AMSK))[tid] = ((const float4*)(amask + b * SQ))[tid];
    if (tid < 32)
        ((float4*)(sm + A_IMSK))[tid] = ((const float4*)(imask + b * LI))[tid];

    float cacc[4][4];
#pragma unroll
    for (int i = 0; i < 4; i++)
#pragma unroll
        for (int j = 0; j < 4; j++) cacc[i][j] = 0.f;
    float mrow[2] = {-1e30f, -1e30f}, ssum[2] = {0.f, 0.f};
    float* corr_sm = (float*)(sm + A_CORR);
    const float* amsk = (const float*)(sm + A_AMSK);
    const float* imsk = (const float*)(sm + A_IMSK);

    {
        cpa_tile64(sb, A_KV0 + KOH, g_Kh + ((size_t)bh * SQ) * DH, tid);
        cpa_tile64(sb, A_KV0 + KOL, g_Kl + ((size_t)bh * SQ) * DH, tid);
        cpa_tile64(sb, A_KV0 + VOH, g_Vh + ((size_t)bh * SQ) * DH, tid);
        cpa_tile64(sb, A_KV0 + VOL, g_Vl + ((size_t)bh * SQ) * DH, tid);
        const __nv_bfloat16* Eg = g_Eh + (size_t)(l0 + 960) * 64;
#pragma unroll
        for (int it = 0; it < 4; it++) {
            int i = tid + it * 256;
            int r = i >> 3, c = (i & 7) * 8;
            cpasync16(sb + A_E0 + (r * PST + c) * 2, Eg + r * 64 + c);
        }
        CP_COMMIT();
    }

    // ======================= main pass =======================
    for (int rt = 0; rt < 16; rt++) {
        const int pb = rt & 1;
        const int kvb = A_KV0 + pb * KVSET;
        const int eb = A_E0 + pb * ESET;
        const int r0 = rt * 64;

        if (rt + 1 < 16) {
            const int nb2 = A_KV0 + (pb ^ 1) * KVSET;
            const int r1 = r0 + 64;
            cpa_tile64(sb, nb2 + KOH, g_Kh + ((size_t)bh * SQ + r1) * DH, tid);
            cpa_tile64(sb, nb2 + KOL, g_Kl + ((size_t)bh * SQ + r1) * DH, tid);
            cpa_tile64(sb, nb2 + VOH, g_Vh + ((size_t)bh * SQ + r1) * DH, tid);
            cpa_tile64(sb, nb2 + VOL, g_Vl + ((size_t)bh * SQ + r1) * DH, tid);
            const __nv_bfloat16* Eg = g_Eh + (size_t)(l0 - r1 + 960) * 64;
            const int eb2 = A_E0 + (pb ^ 1) * ESET;
#pragma unroll
            for (int it = 0; it < 4; it++) {
                int i = tid + it * 256;
                int r = i >> 3, c = (i & 7) * 8;
                cpasync16(sb + eb2 + (r * PST + c) * 2, Eg + r * 64 + c);
            }
            CP_COMMIT();
            CP_WAIT(1);
        } else {
            CP_WAIT(0);
        }
        __syncthreads();

        float sacc[8][4];
        if (warp < 4) {
#pragma unroll
            for (int j = 0; j < 8; j++)
#pragma unroll
                for (int p = 0; p < 4; p++) sacc[j][p] = 0.f;
#pragma unroll
            for (int k = 0; k < 4; k++) {
                const uint32_t ko = (k * 16 + (lane >> 4) * 8) * 2;
                uint32_t aH[4], aL[4];
                ldsm4(aH[0], aH[1], aH[2], aH[3],
                      sb + A_SQH + (wm + (lane & 15)) * PST * 2 + ko);
                ldsm4(aL[0], aL[1], aL[2], aL[3],
                      sb + A_SQL + (wm + (lane & 15)) * PST * 2 + ko);
#pragma unroll
                for (int nb = 0; nb < 4; nb++) {
                    uint32_t bH[4], bL[4];
                    ldsm4(bH[0], bH[1], bH[2], bH[3],
                          sb + kvb + KOH + (nb * 16 + (lane & 15)) * PST * 2 + ko);
                    ldsm4(bL[0], bL[1], bL[2], bL[3],
                          sb + kvb + KOL + (nb * 16 + (lane & 15)) * PST * 2 + ko);
                    mma16816(sacc[2 * nb], aH[0], aH[1], aH[2], aH[3], bH[0], bH[2]);
                    mma16816(sacc[2 * nb], aH[0], aH[1], aH[2], aH[3], bL[0], bL[2]);
                    mma16816(sacc[2 * nb], aL[0], aL[1], aL[2], aL[3], bH[0], bH[2]);
                    mma16816(sacc[2 * nb + 1], aH[0], aH[1], aH[2], aH[3], bH[1], bH[3]);
                    mma16816(sacc[2 * nb + 1], aH[0], aH[1], aH[2], aH[3], bL[1], bL[3]);
                    mma16816(sacc[2 * nb + 1], aL[0], aL[1], aL[2], aL[3], bH[1], bH[3]);
                }
            }
        } else {
            const int isP2 = (warp >= 6);
            const int m0p = (warp - (isP2 ? 6 : 4)) * 32;
            const int srcA = isP2 ? (kvb + KOH) : A_SQH;
            const int dstP = isP2 ? A_SP2 : A_SP1;
#pragma unroll
            for (int ch = 0; ch < 2; ch++) {
                float pacc[2][8][4];
#pragma unroll
                for (int s = 0; s < 2; s++)
#pragma unroll
                    for (int j = 0; j < 8; j++)
#pragma unroll
                        for (int p = 0; p < 4; p++) pacc[s][j][p] = 0.f;
#pragma unroll
                for (int k = 0; k < 4; k++) {
                    const uint32_t ko = (k * 16 + (lane >> 4) * 8) * 2;
                    uint32_t aU[4], aD[4];
                    ldsm4(aU[0], aU[1], aU[2], aU[3],
                          sb + srcA + (m0p + (lane & 15)) * PST * 2 + ko);
                    ldsm4(aD[0], aD[1], aD[2], aD[3],
                          sb + srcA + (m0p + 16 + (lane & 15)) * PST * 2 + ko);
#pragma unroll
                    for (int nb = 0; nb < 4; nb++) {
                        uint32_t be[4];
                        ldsm4(be[0], be[1], be[2], be[3],
                              sb + eb + (ch * 64 + nb * 16 + (lane & 15)) * PST * 2 + ko);
                        mma16816(pacc[0][2 * nb], aU[0], aU[1], aU[2], aU[3], be[0], be[2]);
                        mma16816(pacc[0][2 * nb + 1], aU[0], aU[1], aU[2], aU[3], be[1], be[3]);
                        mma16816(pacc[1][2 * nb], aD[0], aD[1], aD[2], aD[3], be[0], be[2]);
                        mma16816(pacc[1][2 * nb + 1], aD[0], aD[1], aD[2], aD[3], be[1], be[3]);
                    }
                }
#pragma unroll
                for (int s = 0; s < 2; s++)
#pragma unroll
                    for (int j = 0; j < 8; j++) {
                        int l = m0p + s * 16 + g;
                        int w = ch * 64 + 8 * j + 2 * t4;
                        *(uint32_t*)(sm + dstP + (l * P12 + w) * 2) =
                            pk2(pacc[s][j][0], pacc[s][j][1]);
                        *(uint32_t*)(sm + dstP + ((l + 8) * P12 + w) * 2) =
                            pk2(pacc[s][j][2], pacc[s][j][3]);
                    }
            }
        }
        __syncthreads();

        if (warp < 4) {
            const int l = wm + g;
#pragma unroll
            for (int j = 0; j < 8; j++) {
                const int r = 8 * j + 2 * t4;
                const int w = l - r + 63;
                sacc[j][0] = (sacc[j][0] + ldbf(sm, A_SP1, l * P12 + w)
                              + ldbf(sm, A_SP2, r * P12 + w)) * 0.125f + amsk[r0 + r];
                sacc[j][1] = (sacc[j][1] + ldbf(sm, A_SP1, l * P12 + w - 1)
                              + ldbf(sm, A_SP2, (r + 1) * P12 + w - 1)) * 0.125f + amsk[r0 + r + 1];
                sacc[j][2] = (sacc[j][2] + ldbf(sm, A_SP1, (l + 8) * P12 + w + 8)
                              + ldbf(sm, A_SP2, r * P12 + w + 8)) * 0.125f + amsk[r0 + r];
                sacc[j][3] = (sacc[j][3] + ldbf(sm, A_SP1, (l + 8) * P12 + w + 7)
                              + ldbf(sm, A_SP2, (r + 1) * P12 + w + 7)) * 0.125f + amsk[r0 + r + 1];
            }
            float mt0 = -1e30f, mt1 = -1e30f;
#pragma unroll
            for (int j = 0; j < 8; j++) {
                mt0 = fmaxf(mt0, fmaxf(sacc[j][0], sacc[j][1]));
                mt1 = fmaxf(mt1, fmaxf(sacc[j][2], sacc[j][3]));
            }
            mt0 = fmaxf(mt0, __shfl_xor_sync(0xffffffffu, mt0, 1));
            mt0 = fmaxf(mt0, __shfl_xor_sync(0xffffffffu, mt0, 2));
            mt1 = fmaxf(mt1, __shfl_xor_sync(0xffffffffu, mt1, 1));
            mt1 = fmaxf(mt1, __shfl_xor_sync(0xffffffffu, mt1, 2));
            float mn0 = fmaxf(mrow[0], mt0), mn1 = fmaxf(mrow[1], mt1);
            float cr0 = __expf(mrow[0] - mn0), cr1 = __expf(mrow[1] - mn1);
            mrow[0] = mn0; mrow[1] = mn1;
            float ps0 = 0.f, ps1 = 0.f;
#pragma unroll
            for (int j = 0; j < 8; j++) {
                float p00 = __expf(sacc[j][0] - mn0), p01 = __expf(sacc[j][1] - mn0);
                float p10 = __expf(sacc[j][2] - mn1), p11 = __expf(sacc[j][3] - mn1);
                ps0 += p00 + p01; ps1 += p10 + p11;
                int cidx = 8 * j + 2 * t4;
                uint32_t h0 = pk2(p00, p01), h1 = pk2(p10, p11);
                *(uint32_t*)(sm + A_SPH + (l * PST + cidx) * 2) = h0;
                *(uint32_t*)(sm + A_SPH + ((l + 8) * PST + cidx) * 2) = h1;
                __nv_bfloat162 hh0 = *(__nv_bfloat162*)&h0;
                __nv_bfloat162 hh1 = *(__nv_bfloat162*)&h1;
                *(uint32_t*)(sm + A_SPL + (l * PST + cidx) * 2) =
                    pk2(p00 - __bfloat162float(hh0.x), p01 - __bfloat162float(hh0.y));
                *(uint32_t*)(sm + A_SPL + ((l + 8) * PST + cidx) * 2) =
                    pk2(p10 - __bfloat162float(hh1.x), p11 - __bfloat162float(hh1.y));
            }
            ps0 += __shfl_xor_sync(0xffffffffu, ps0, 1);
            ps0 += __shfl_xor_sync(0xffffffffu, ps0, 2);
            ps1 += __shfl_xor_sync(0xffffffffu, ps1, 1);
            ps1 += __shfl_xor_sync(0xffffffffu, ps1, 2);
            ssum[0] = ssum[0] * cr0 + ps0;
            ssum[1] = ssum[1] * cr1 + ps1;
            if (t4 == 0) { corr_sm[l] = cr0; corr_sm[l + 8] = cr1; }
        }
        __syncthreads();

        {
            float c0r = corr_sm[wm2 + g], c1r = corr_sm[wm2 + 8 + g];
#pragma unroll
            for (int nf = 0; nf < 4; nf++) {
                cacc[nf][0] *= c0r; cacc[nf][1] *= c0r;
                cacc[nf][2] *= c1r; cacc[nf][3] *= c1r;
            }
#pragma unroll
            for (int kk = 0; kk < 4; kk++) {
                const uint32_t ko = (kk * 16 + (lane >> 4) * 8) * 2;
                uint32_t aPh[4], aPl[4];
                ldsm4(aPh[0], aPh[1], aPh[2], aPh[3],
                      sb + A_SPH + (wm2 + (lane & 15)) * PST * 2 + ko);
                ldsm4(aPl[0], aPl[1], aPl[2], aPl[3],
                      sb + A_SPL + (wm2 + (lane & 15)) * PST * 2 + ko);
#pragma unroll
                for (int dh = 0; dh < 2; dh++) {
                    const uint32_t trow = (kk * 16 + (lane & 7) + 8 * ((lane >> 3) & 1)) * PST;
                    const uint32_t tcol = wn2 + dh * 16 + ((lane >> 4) & 1) * 8;
                    uint32_t bh2[4], bl2[4];
                    ldsm4t(bh2[0], bh2[1], bh2[2], bh2[3],
                           sb + kvb + VOH + (trow + tcol) * 2);
                    ldsm4t(bl2[0], bl2[1], bl2[2], bl2[3],
                           sb + kvb + VOL + (trow + tcol) * 2);
                    const int nf = dh * 2;
                    mma16816(cacc[nf], aPh[0], aPh[1], aPh[2], aPh[3], bh2[0], bh2[1]);
                    mma16816(cacc[nf], aPh[0], aPh[1], aPh[2], aPh[3], bl2[0], bl2[1]);
                    mma16816(cacc[nf], aPl[0], aPl[1], aPl[2], aPl[3], bh2[0], bh2[1]);
                    mma16816(cacc[nf + 1], aPh[0], aPh[1], aPh[2], aPh[3], bh2[2], bh2[3]);
                    mma16816(cacc[nf + 1], aPh[0], aPh[1], aPh[2], aPh[3], bl2[2], bl2[3]);
                    mma16816(cacc[nf + 1], aPl[0], aPl[1], aPl[2], aPl[3], bh2[2], bh2[3]);
                }
            }
        }
        __syncthreads();
    }

    {
        float* stash = (float*)(sm + A_SP1);
#pragma unroll
        for (int nf = 0; nf < 4; nf++) {
            int d = wn2 + 8 * nf + 2 * t4;
            stash[(wm2 + g) * 68 + d] = cacc[nf][0];
            stash[(wm2 + g) * 68 + d + 1] = cacc[nf][1];
            stash[(wm2 + 8 + g) * 68 + d] = cacc[nf][2];
            stash[(wm2 + 8 + g) * 68 + d + 1] = cacc[nf][3];
            cacc[nf][0] = cacc[nf][1] = cacc[nf][2] = cacc[nf][3] = 0.f;
        }
        if (warp < 4 && t4 == 0) {
            ((float*)(sm + A_SSM))[wm + g] = ssum[0];
            ((float*)(sm + A_SSM))[wm + g + 8] = ssum[1];
        }
        mrow[0] = mrow[1] = -1e30f; ssum[0] = ssum[1] = 0.f;
    }

    // ======================= instruct pass =======================
    for (int rt = 0; rt < 2; rt++) {
        const int r0 = rt * 64;
        const int kvb = A_KV0;
        __syncthreads();
        cp_tile64(sm, kvb + KOH, g_IKh + ((size_t)bh * LI + r0) * DH, tid);
        cp_tile64(sm, kvb + KOL, g_IKl + ((size_t)bh * LI + r0) * DH, tid);
        cp_tile64(sm, kvb + VOH, g_IVh + ((size_t)bh * LI + r0) * DH, tid);
        cp_tile64(sm, kvb + VOL, g_IVl + ((size_t)bh * LI + r0) * DH, tid);
        __syncthreads();

        if (warp < 4) {
            float sacc[8][4];
#pragma unroll
            for (int j = 0; j < 8; j++)
#pragma unroll
                for (int p = 0; p < 4; p++) sacc[j][p] = 0.f;
#pragma unroll
            for (int k = 0; k < 4; k++) {
                const uint32_t ko = (k * 16 + (lane >> 4) * 8) * 2;
                uint32_t aH[4], aL[4];
                ldsm4(aH[0], aH[1], aH[2], aH[3],
                      sb + A_SQH + (wm + (lane & 15)) * PST * 2 + ko);
                ldsm4(aL[0], aL[1], aL[2], aL[3],
                      sb + A_SQL + (wm + (lane & 15)) * PST * 2 + ko);
#pragma unroll
                for (int nb = 0; nb < 4; nb++) {
                    uint32_t bH[4], bL[4];
                    ldsm4(bH[0], bH[1], bH[2], bH[3],
                          sb + kvb + KOH + (nb * 16 + (lane & 15)) * PST * 2 + ko);
                    ldsm4(bL[0], bL[1], bL[2], bL[3],
                          sb + kvb + KOL + (nb * 16 + (lane & 15)) * PST * 2 + ko);
                    mma16816(sacc[2 * nb], aH[0], aH[1], aH[2], aH[3], bH[0], bH[2]);
                    mma16816(sacc[2 * nb], aH[0], aH[1], aH[2], aH[3], bL[0], bL[2]);
                    mma16816(sacc[2 * nb], aL[0], aL[1], aL[2], aL[3], bH[0], bH[2]);
                    mma16816(sacc[2 * nb + 1], aH[0], aH[1], aH[2], aH[3], bH[1], bH[3]);
                    mma16816(sacc[2 * nb + 1], aH[0], aH[1], aH[2], aH[3], bL[1], bL[3]);
                    mma16816(sacc[2 * nb + 1], aL[0], aL[1], aL[2], aL[3], bH[1], bH[3]);
                }
            }
            const int l = wm + g;
            float mt0 = -1e30f, mt1 = -1e30f;
#pragma unroll
            for (int j = 0; j < 8; j++) {
                const int r = 8 * j + 2 * t4;
                sacc[j][0] = sacc[j][0] * 0.125f + imsk[r0 + r];
                sacc[j][1] = sacc[j][1] * 0.125f + imsk[r0 + r + 1];
                sacc[j][2] = sacc[j][2] * 0.125f + imsk[r0 + r];
                sacc[j][3] = sacc[j][3] * 0.125f + imsk[r0 + r + 1];
                mt0 = fmaxf(mt0, fmaxf(sacc[j][0], sacc[j][1]));
                mt1 = fmaxf(mt1, fmaxf(sacc[j][2], sacc[j][3]));
            }
            mt0 = fmaxf(mt0, __shfl_xor_sync(0xffffffffu, mt0, 1));
            mt0 = fmaxf(mt0, __shfl_xor_sync(0xffffffffu, mt0, 2));
            mt1 = fmaxf(mt1, __shfl_xor_sync(0xffffffffu, mt1, 1));
            mt1 = fmaxf(mt1, __shfl_xor_sync(0xffffffffu, mt1, 2));
            float mn0 = fmaxf(mrow[0], mt0), mn1 = fmaxf(mrow[1], mt1);
            float cr0 = __expf(mrow[0] - mn0), cr1 = __expf(mrow[1] - mn1);
            mrow[0] = mn0; mrow[1] = mn1;
            float ps0 = 0.f, ps1 = 0.f;
#pragma unroll
            for (int j = 0; j < 8; j++) {
                float p00 = __expf(sacc[j][0] - mn0), p01 = __expf(sacc[j][1] - mn0);
                float p10 = __expf(sacc[j][2] - mn1), p11 = __expf(sacc[j][3] - mn1);
                ps0 += p00 + p01; ps1 += p10 + p11;
                int cidx = 8 * j + 2 * t4;
                uint32_t h0 = pk2(p00, p01), h1 = pk2(p10, p11);
                *(uint32_t*)(sm + A_SPH + (l * PST + cidx) * 2) = h0;
                *(uint32_t*)(sm + A_SPH + ((l + 8) * PST + cidx) * 2) = h1;
                __nv_bfloat162 hh0 = *(__nv_bfloat162*)&h0;
                __nv_bfloat162 hh1 = *(__nv_bfloat162*)&h1;
                *(uint32_t*)(sm + A_SPL + (l * PST + cidx) * 2) =
                    pk2(p00 - __bfloat162float(hh0.x), p01 - __bfloat162float(hh0.y));
                *(uint32_t*)(sm + A_SPL + ((l + 8) * PST + cidx) * 2) =
                    pk2(p10 - __bfloat162float(hh1.x), p11 - __bfloat162float(hh1.y));
            }
            ps0 += __shfl_xor_sync(0xffffffffu, ps0, 1);
            ps0 += __shfl_xor_sync(0xffffffffu, ps0, 2);
            ps1 += __shfl_xor_sync(0xffffffffu, ps1, 1);
            ps1 += __shfl_xor_sync(0xffffffffu, ps1, 2);
            ssum[0] = ssum[0] * cr0 + ps0;
            ssum[1] = ssum[1] * cr1 + ps1;
            if (t4 == 0) { corr_sm[l] = cr0; corr_sm[l + 8] = cr1; }
        }
        __syncthreads();

        {
            float c0r = corr_sm[wm2 + g], c1r = corr_sm[wm2 + 8 + g];
#pragma unroll
            for (int nf = 0; nf < 4; nf++) {
                cacc[nf][0] *= c0r; cacc[nf][1] *= c0r;
                cacc[nf][2] *= c1r; cacc[nf][3] *= c1r;
            }
#pragma unroll
            for (int kk = 0; kk < 4; kk++) {
                const uint32_t ko = (kk * 16 + (lane >> 4) * 8) * 2;
                uint32_t aPh[4], aPl[4];
                ldsm4(aPh[0], aPh[1], aPh[2], aPh[3],
                      sb + A_SPH + (wm2 + (lane & 15)) * PST * 2 + ko);
                ldsm4(aPl[0], aPl[1], aPl[2], aPl[3],
                      sb + A_SPL + (wm2 + (lane & 15)) * PST * 2 + ko);
#pragma unroll
                for (int dh = 0; dh < 2; dh++) {
                    const uint32_t trow = (kk * 16 + (lane & 7) + 8 * ((lane >> 3) & 1)) * PST;
                    const uint32_t tcol = wn2 + dh * 16 + ((lane >> 4) & 1) * 8;
                    uint32_t bh2[4], bl2[4];
                    ldsm4t(bh2[0], bh2[1], bh2[2], bh2[3],
                           sb + kvb + VOH + (trow + tcol) * 2);
                    ldsm4t(bl2[0], bl2[1], bl2[2], bl2[3],
                           sb + kvb + VOL + (trow + tcol) * 2);
                    const int nf = dh * 2;
                    mma16816(cacc[nf], aPh[0], aPh[1], aPh[2], aPh[3], bh2[0], bh2[1]);
                    mma16816(cacc[nf], aPh[0], aPh[1], aPh[2], aPh[3], bl2[0], bl2[1]);
                    mma16816(cacc[nf], aPl[0], aPl[1], aPl[2], aPl[3], bh2[0], bh2[1]);
                    mma16816(cacc[nf + 1], aPh[0], aPh[1], aPh[2], aPh[3], bh2[2], bh2[3]);
                    mma16816(cacc[nf + 1], aPh[0], aPh[1], aPh[2], aPh[3], bl2[2], bl2[3]);
                    mma16816(cacc[nf + 1], aPl[0], aPl[1], aPl[2], aPl[3], bh2[2], bh2[3]);
                }
            }
        }
    }

    __syncthreads();
    if (warp < 4 && t4 == 0) {
        ((float*)(sm + A_SSI))[wm + g] = ssum[0];
        ((float*)(sm + A_SSI))[wm + g + 8] = ssum[1];
    }
    __syncthreads();

    {
        const float tg = tanhf(gate[h]);
        const float* stash = (const float*)(sm + A_SP1);
        const float* ssmv = (const float*)(sm + A_SSM);
        const float* ssiv = (const float*)(sm + A_SSI);
        const float rnm0 = 1.f / ssmv[wm2 + g], rni0 = tg / ssiv[wm2 + g];
        const float rnm1 = 1.f / ssmv[wm2 + 8 + g], rni1 = tg / ssiv[wm2 + 8 + g];
#pragma unroll
        for (int nf = 0; nf < 4; nf++) {
            const int d = wn2 + 8 * nf + 2 * t4;
            float2 o0, o1;
            o0.x = stash[(wm2 + g) * 68 + d] * rnm0 + cacc[nf][0] * rni0;
            o0.y = stash[(wm2 + g) * 68 + d + 1] * rnm0 + cacc[nf][1] * rni0;
            o1.x = stash[(wm2 + 8 + g) * 68 + d] * rnm1 + cacc[nf][2] * rni1;
            o1.y = stash[(wm2 + 8 + g) * 68 + d + 1] * rnm1 + cacc[nf][3] * rni1;
            *(float2*)(outp + ((size_t)(b * SQ + l0 + wm2 + g)) * HIDDEN + h * DH + d) = o0;
            *(float2*)(outp + ((size_t)(b * SQ + l0 + wm2 + 8 + g)) * HIDDEN + h * DH + d) = o1;
        }
    }
}

// ---------------------------------------------------------------------------
extern "C" void kernel_launch(void* const* d_in, const int* in_sizes, int n_in,
                              void* d_out, int out_size)
{
    (void)in_sizes; (void)n_in; (void)out_size;
    const float* hs    = (const float*)d_in[0];
    const float* amask = (const float*)d_in[1];
    const float* ihs   = (const float*)d_in[2];
    const float* imask = (const float*)d_in[3];
    const float* Wq    = (const float*)d_in[4];
    const float* bq    = (const float*)d_in[5];
    const float* Wk    = (const float*)d_in[6];
    const float* bk    = (const float*)d_in[7];
    const float* Wv    = (const float*)d_in[8];
    const float* bv    = (const float*)d_in[9];
    const float* gate  = (const float*)d_in[10];
    const float* dist  = (const float*)d_in[11];
    float* out = (float*)d_out;

    __nv_bfloat16 *qh, *ql, *kh, *kl, *vh, *vl, *ikh, *ikl, *ivh, *ivl, *eh;
    __nv_bfloat16 *xc, *ixc, *wc;
    cudaGetSymbolAddress((void**)&qh, g_Qh);
    cudaGetSymbolAddress((void**)&ql, g_Ql);
    cudaGetSymbolAddress((void**)&kh, g_Kh);
    cudaGetSymbolAddress((void**)&kl, g_Kl);
    cudaGetSymbolAddress((void**)&vh, g_Vh);
    cudaGetSymbolAddress((void**)&vl, g_Vl);
    cudaGetSymbolAddress((void**)&ikh, g_IKh);
    cudaGetSymbolAddress((void**)&ikl, g_IKl);
    cudaGetSymbolAddress((void**)&ivh, g_IVh);
    cudaGetSymbolAddress((void**)&ivl, g_IVl);
    cudaGetSymbolAddress((void**)&eh, g_Eh);
    cudaGetSymbolAddress((void**)&xc, g_Xcat);
    cudaGetSymbolAddress((void**)&ixc, g_IXcat);
    cudaGetSymbolAddress((void**)&wc, g_Wcat);

    cudaFuncSetAttribute(gemm_mma, cudaFuncAttributeMaxDynamicSharedMemorySize, GEMM_SMEM);
    cudaFuncSetAttribute(attn_mma, cudaFuncAttributeMaxDynamicSharedMemorySize, A_TOTAL);

    conv_all<<<NX_MAIN + NX_INST + NX_E, 256>>>((const float4*)hs, xc,
                                                (const float4*)ihs, ixc, dist, eh);
    conv_w<<<dim3(32, 32, 3), 256>>>(Wq, Wk, Wv, wc);

    gemm_mma<<<416, 256, GEMM_SMEM>>>(xc, ixc, wc, bq, bk, bv,
                                      qh, ql, kh, kl, vh, vl,
                                      ikh, ikl, ivh, ivl);

    attn_mma<<<dim3(SQ / 64, BHN), 256, A_TOTAL>>>(amask, imask, gate, out);
}